// round 4
// baseline (speedup 1.0000x reference)
#include <cuda_runtime.h>
#include <cstdint>

#define B_  32
#define T_  512
#define D_  2048
#define H_  128
#define G_  512
#define M_FWD (B_ * T_)      // 16384

// ---------------- scratch (device globals: no allocations allowed) ----------
__device__ float g_xp[M_FWD * G_];      // forward gate preactivations  [B*T, 4H]
__device__ float g_gb[B_ * G_];         // backward gate preacts at t=T-1 [B, 4H]
__device__ float g_last[B_ * 2 * H_];   // [h_fwd(T-1) | h_bwd(T-1)]     [B, 2H]

extern __shared__ unsigned char dynsmem[];

__device__ __forceinline__ uint32_t f2tf32(float x) {
    uint32_t u;
    asm("cvt.rna.tf32.f32 %0, %1;" : "=r"(u) : "f"(x));
    return u;
}

__device__ __forceinline__ float sigmoidf_(float x) {
    return 1.0f / (1.0f + expf(-x));
}

// ============================================================================
// tf32 GEMM: C[M x 512] = A[M x 2048] @ W^T + bias0 + bias1
//   A: row stride lda (elements), rows >= Mreal are treated as zero
//   W: [512][2048] row-major (i.e. both operands K-contiguous -> mma row.col)
//   C: row-major, ldc = 512
// Tiles: BM=128, BN=128, BK=32; 256 threads = 8 warps (4 m x 2 n),
// warp tile 32x64, mma m16n8k8 tf32. Double-buffered smem via register staging.
// ============================================================================
__global__ __launch_bounds__(256)
void gemm_tf32(const float* __restrict__ A, int lda, int Mreal,
               const float* __restrict__ W,
               const float* __restrict__ bias0, const float* __restrict__ bias1,
               float* __restrict__ C)
{
    constexpr int BK = 32, PK = 36;          // padded k-stride (conflict-free)
    constexpr int NIT = D_ / BK;             // 64 mainloop iterations
    uint32_t* As = (uint32_t*)dynsmem;       // [2][128*PK]
    uint32_t* Bs = As + 2 * 128 * PK;        // [2][128*PK]

    const int tid  = threadIdx.x;
    const int wid  = tid >> 5, lane = tid & 31;
    const int wm   = wid & 3,  wn   = wid >> 2;     // warp grid 4 x 2
    const int g    = lane >> 2, tg  = lane & 3;
    const int m0   = blockIdx.x * 128, n0 = blockIdx.y * 128;

    const int lr = tid >> 3;          // 0..31 : row within a 32-row group
    const int lc = (tid & 7) * 4;     // 0,4,...,28 : k offset (float4)

    float4 ra[4], rb[4];
    float acc[2][8][4];
    #pragma unroll
    for (int i = 0; i < 2; i++)
        #pragma unroll
        for (int j = 0; j < 8; j++)
            #pragma unroll
            for (int r = 0; r < 4; r++) acc[i][j][r] = 0.0f;

    // ---- prologue: load tile 0 -> regs -> smem buf 0 ----
    {
        const int k = 0 + lc;
        #pragma unroll
        for (int i = 0; i < 4; i++) {
            const int r  = lr + i * 32;
            const int gm = m0 + r;
            if (gm < Mreal) ra[i] = *(const float4*)(A + (long)gm * lda + k);
            else            ra[i] = make_float4(0.f, 0.f, 0.f, 0.f);
            rb[i] = *(const float4*)(W + (n0 + r) * D_ + k);
        }
        uint32_t* as = As;
        uint32_t* bs = Bs;
        #pragma unroll
        for (int i = 0; i < 4; i++) {
            const int r = lr + i * 32;
            uint32_t* pa = as + r * PK + lc;
            pa[0] = f2tf32(ra[i].x); pa[1] = f2tf32(ra[i].y);
            pa[2] = f2tf32(ra[i].z); pa[3] = f2tf32(ra[i].w);
            uint32_t* pb = bs + r * PK + lc;
            pb[0] = f2tf32(rb[i].x); pb[1] = f2tf32(rb[i].y);
            pb[2] = f2tf32(rb[i].z); pb[3] = f2tf32(rb[i].w);
        }
    }
    __syncthreads();

    for (int it = 0; it < NIT; it++) {
        const int cur = it & 1;

        // ---- stage next tile into registers (global loads fly during mma) ----
        if (it + 1 < NIT) {
            const int k = (it + 1) * BK + lc;
            #pragma unroll
            for (int i = 0; i < 4; i++) {
                const int r  = lr + i * 32;
                const int gm = m0 + r;
                if (gm < Mreal) ra[i] = *(const float4*)(A + (long)gm * lda + k);
                else            ra[i] = make_float4(0.f, 0.f, 0.f, 0.f);
                rb[i] = *(const float4*)(W + (n0 + r) * D_ + k);
            }
        }

        // ---- compute on current buffer ----
        {
            const uint32_t* as = As + cur * 128 * PK;
            const uint32_t* bs = Bs + cur * 128 * PK;
            #pragma unroll
            for (int kk = 0; kk < 4; kk++) {
                uint32_t af[2][4], bf[8][2];
                #pragma unroll
                for (int mf = 0; mf < 2; mf++) {
                    const int r0 = wm * 32 + mf * 16;
                    const uint32_t* p = as + r0 * PK + kk * 8 + tg;
                    af[mf][0] = p[g * PK];
                    af[mf][1] = p[(8 + g) * PK];
                    af[mf][2] = p[g * PK + 4];
                    af[mf][3] = p[(8 + g) * PK + 4];
                }
                #pragma unroll
                for (int nf = 0; nf < 8; nf++) {
                    const int c0 = wn * 64 + nf * 8;
                    const uint32_t* p = bs + (c0 + g) * PK + kk * 8 + tg;
                    bf[nf][0] = p[0];
                    bf[nf][1] = p[4];
                }
                #pragma unroll
                for (int mf = 0; mf < 2; mf++)
                    #pragma unroll
                    for (int nf = 0; nf < 8; nf++)
                        asm volatile(
                            "mma.sync.aligned.m16n8k8.row.col.f32.tf32.tf32.f32 "
                            "{%0,%1,%2,%3}, {%4,%5,%6,%7}, {%8,%9}, {%0,%1,%2,%3};"
                            : "+f"(acc[mf][nf][0]), "+f"(acc[mf][nf][1]),
                              "+f"(acc[mf][nf][2]), "+f"(acc[mf][nf][3])
                            : "r"(af[mf][0]), "r"(af[mf][1]),
                              "r"(af[mf][2]), "r"(af[mf][3]),
                              "r"(bf[nf][0]), "r"(bf[nf][1]));
            }
        }

        // ---- drain staged tile into the other buffer ----
        if (it + 1 < NIT) {
            const int nb = (it + 1) & 1;
            uint32_t* as = As + nb * 128 * PK;
            uint32_t* bs = Bs + nb * 128 * PK;
            #pragma unroll
            for (int i = 0; i < 4; i++) {
                const int r = lr + i * 32;
                uint32_t* pa = as + r * PK + lc;
                pa[0] = f2tf32(ra[i].x); pa[1] = f2tf32(ra[i].y);
                pa[2] = f2tf32(ra[i].z); pa[3] = f2tf32(ra[i].w);
                uint32_t* pb = bs + r * PK + lc;
                pb[0] = f2tf32(rb[i].x); pb[1] = f2tf32(rb[i].y);
                pb[2] = f2tf32(rb[i].z); pb[3] = f2tf32(rb[i].w);
            }
        }
        __syncthreads();
    }

    // ---- epilogue: add both biases, store ----
    #pragma unroll
    for (int mf = 0; mf < 2; mf++) {
        #pragma unroll
        for (int nf = 0; nf < 8; nf++) {
            const int col = n0 + wn * 64 + nf * 8 + 2 * tg;
            const float bs0 = bias0[col]     + bias1[col];
            const float bs1 = bias0[col + 1] + bias1[col + 1];
            const int r0 = m0 + wm * 32 + mf * 16 + g;
            if (r0 < Mreal) {
                float2 v; v.x = acc[mf][nf][0] + bs0; v.y = acc[mf][nf][1] + bs1;
                *(float2*)(C + (long)r0 * G_ + col) = v;
            }
            const int r1 = r0 + 8;
            if (r1 < Mreal) {
                float2 v; v.x = acc[mf][nf][2] + bs0; v.y = acc[mf][nf][3] + bs1;
                *(float2*)(C + (long)r1 * G_ + col) = v;
            }
        }
    }
}

// ============================================================================
// Forward LSTM recurrence: one CTA per batch element, 512 threads
// (thread j owns gate row j). W_hh rows [0,416) live in smem (row stride 132
// floats -> conflict-free LDS.128); rows [416,512) (warps 13..15) stream from
// L2 (same lines shared by all 32 CTAs). No inter-CTA sync anywhere.
// ============================================================================
#define SMROWS 416
#define WPAD   132

__global__ __launch_bounds__(512)
void lstm_fwd(const float* __restrict__ xp, const float* __restrict__ Whh,
              float* __restrict__ last)
{
    float* W_s    = (float*)dynsmem;             // [SMROWS][WPAD]
    float* h_s    = W_s + SMROWS * WPAD;         // [128]
    float* gate_s = h_s + 128;                   // [512]

    const int tid = threadIdx.x;
    const int b   = blockIdx.x;

    // stage W_hh rows [0, SMROWS) into padded smem (coalesced gmem reads)
    for (int idx = tid; idx < SMROWS * 128; idx += 512) {
        const int j = idx >> 7, k = idx & 127;
        W_s[j * WPAD + k] = Whh[idx];
    }
    if (tid < 128) h_s[tid] = 0.0f;
    float c = 0.0f;
    __syncthreads();

    const float*  xprow = xp + (long)b * T_ * G_;
    const float4* wp    = (const float4*)(W_s + tid * WPAD);       // smem rows
    const float4* wg    = (const float4*)(Whh + tid * 128);        // gmem rows

    for (int t = 0; t < T_; t++) {
        float acc = xprow[t * G_ + tid];
        if (tid < SMROWS) {
            #pragma unroll
            for (int k4 = 0; k4 < 32; k4++) {
                const float4 w  = wp[k4];
                const float4 hh = *(const float4*)(h_s + k4 * 4);  // broadcast
                acc += w.x * hh.x + w.y * hh.y + w.z * hh.z + w.w * hh.w;
            }
        } else {
            #pragma unroll
            for (int k4 = 0; k4 < 32; k4++) {
                const float4 w  = __ldg(wg + k4);
                const float4 hh = *(const float4*)(h_s + k4 * 4);
                acc += w.x * hh.x + w.y * hh.y + w.z * hh.z + w.w * hh.w;
            }
        }
        gate_s[tid] = acc;
        __syncthreads();
        if (tid < 128) {
            const float gi = gate_s[tid],       gf = gate_s[128 + tid];
            const float gg = gate_s[256 + tid], go = gate_s[384 + tid];
            c = sigmoidf_(gf) * c + sigmoidf_(gi) * tanhf(gg);
            const float h = sigmoidf_(go) * tanhf(c);
            h_s[tid] = h;
            if (t == T_ - 1) last[b * (2 * H_) + tid] = h;
        }
        __syncthreads();
    }
}

// ============================================================================
// Backward direction, single step from zero state (reverse scan output at
// t = T-1):  c = sig(i)*tanh(g),  h = sig(o)*tanh(c).  Forget gate * c0 = 0.
// ============================================================================
__global__ void bwd_last(const float* __restrict__ gb, float* __restrict__ last)
{
    const int b = blockIdx.x, j = threadIdx.x;   // 32 x 128
    const float* r = gb + b * G_;
    const float ci = sigmoidf_(r[j]) * tanhf(r[256 + j]);
    last[b * (2 * H_) + H_ + j] = sigmoidf_(r[384 + j]) * tanhf(ci);
}

// ============================================================================
// MLP head + softmax: one CTA per batch row (tiny).
// ============================================================================
__global__ void head_kernel(const float* __restrict__ last,
                            const float* __restrict__ W1, const float* __restrict__ b1,
                            const float* __restrict__ W2, const float* __restrict__ b2,
                            const float* __restrict__ W3, const float* __restrict__ b3,
                            float* __restrict__ out)
{
    __shared__ float v[256], u[256], w2s[64], lg[11];
    const int b = blockIdx.x, tid = threadIdx.x;   // 256 threads

    v[tid] = last[b * 256 + tid];
    __syncthreads();

    float a = b1[tid];
    #pragma unroll 8
    for (int k = 0; k < 256; k++) a += W1[tid * 256 + k] * v[k];
    u[tid] = a;
    __syncthreads();

    if (tid < 64) {
        float s = b2[tid];
        #pragma unroll 8
        for (int k = 0; k < 256; k++) s += W2[tid * 256 + k] * u[k];
        w2s[tid] = s;
    }
    __syncthreads();

    if (tid < 11) {
        float s = b3[tid];
        #pragma unroll
        for (int k = 0; k < 64; k++) s += W3[tid * 64 + k] * w2s[k];
        lg[tid] = s;
    }
    __syncthreads();

    if (tid == 0) {
        float mx = lg[0];
        for (int i = 1; i < 11; i++) mx = fmaxf(mx, lg[i]);
        float e[11], sum = 0.0f;
        for (int i = 0; i < 11; i++) { e[i] = expf(lg[i] - mx); sum += e[i]; }
        const float inv = 1.0f / sum;
        for (int i = 0; i < 11; i++) out[b * 11 + i] = e[i] * inv;
    }
}

// ============================================================================
extern "C" void kernel_launch(void* const* d_in, const int* in_sizes, int n_in,
                              void* d_out, int out_size)
{
    const float* x    = (const float*)d_in[0];
    const float* Wihf = (const float*)d_in[1];
    const float* Whhf = (const float*)d_in[2];
    const float* bihf = (const float*)d_in[3];
    const float* bhhf = (const float*)d_in[4];
    const float* Wihb = (const float*)d_in[5];
    const float* Whhb = (const float*)d_in[6];  (void)Whhb;  // h0=0: unused
    const float* bihb = (const float*)d_in[7];
    const float* bhhb = (const float*)d_in[8];
    const float* W1 = (const float*)d_in[9];   const float* b1 = (const float*)d_in[10];
    const float* W2 = (const float*)d_in[11];  const float* b2 = (const float*)d_in[12];
    const float* W3 = (const float*)d_in[13];  const float* b3 = (const float*)d_in[14];
    float* out = (float*)d_out;

    void* p;
    cudaGetSymbolAddress(&p, g_xp);   float* xp   = (float*)p;
    cudaGetSymbolAddress(&p, g_gb);   float* gb   = (float*)p;
    cudaGetSymbolAddress(&p, g_last); float* last = (float*)p;

    const int gemm_smem = 2 * 2 * 128 * 36 * (int)sizeof(uint32_t);   // 73728
    const int lstm_smem = (SMROWS * WPAD + 128 + 512) * (int)sizeof(float); // 222208
    cudaFuncSetAttribute(gemm_tf32, cudaFuncAttributeMaxDynamicSharedMemorySize, gemm_smem);
    cudaFuncSetAttribute(lstm_fwd,  cudaFuncAttributeMaxDynamicSharedMemorySize, lstm_smem);

    // forward input projection: [16384 x 2048] @ W_ih_f^T + b_ih_f + b_hh_f
    dim3 gf(M_FWD / 128, G_ / 128);
    gemm_tf32<<<gf, 256, gemm_smem>>>(x, D_, M_FWD, Wihf, bihf, bhhf, xp);

    // backward direction needs only t = T-1 rows: A row b at x[b][T-1][:]
    dim3 gbk(1, G_ / 128);
    gemm_tf32<<<gbk, 256, gemm_smem>>>(x + (long)(T_ - 1) * D_, T_ * D_, B_,
                                       Wihb, bihb, bhhb, gb);

    bwd_last<<<B_, 128>>>(gb, last);
    lstm_fwd<<<B_, 512, lstm_smem>>>(xp, Whhf, last);
    head_kernel<<<B_, 256>>>(last, W1, b1, W2, b2, W3, b3, out);
}

// round 8
// speedup vs baseline: 1.8589x; 1.8589x over previous
#include <cuda_runtime.h>
#include <cuda_fp16.h>
#include <cstdint>

#define B_  32
#define T_  512
#define D_  2048
#define H_  128
#define G_  512
#define M_FWD (B_ * T_)

typedef unsigned long long ull;

__device__ float  g_xp[M_FWD * G_];       // forward gate preacts [B*T, 4H]
__device__ float  g_last[B_ * 2 * H_];    // [h_fwd | h_bwd]
__device__ __half g_Ah[M_FWD * D_];       // fp16 copy of inputs
__device__ __half g_Wh[G_ * D_];          // fp16 copy of W_ih_f

extern __shared__ unsigned char dynsmem[];

// ---------------- helpers ---------------------------------------------------
__device__ __forceinline__ uint32_t smem_u32(const void* p) {
    uint32_t a;
    asm("{ .reg .u64 t; cvta.to.shared.u64 t, %1; cvt.u32.u64 %0, t; }"
        : "=r"(a) : "l"(p));
    return a;
}
__device__ __forceinline__ void fma2(ull& d, ull a, ull b) {
    asm("fma.rn.f32x2 %0, %1, %2, %0;" : "+l"(d) : "l"(a), "l"(b));
}
__device__ __forceinline__ float2 unpk(ull v) {
    float2 r; asm("mov.b64 {%0,%1}, %2;" : "=f"(r.x), "=f"(r.y) : "l"(v)); return r;
}
// same activation source as R1 (which passed at 3.8e-5 under harness flags)
__device__ __forceinline__ float fsig(float x)  { return 1.0f / (1.0f + expf(-x)); }
__device__ __forceinline__ float ftanh(float x) { return tanhf(x); }

#define SWZ128(o) ((o) ^ (((o) >> 3) & 0x70))

#define LDSM_X4(r0, r1, r2, r3, a) \
    asm volatile("ldmatrix.sync.aligned.m8n8.x4.shared.b16 {%0,%1,%2,%3}, [%4];" \
                 : "=r"(r0), "=r"(r1), "=r"(r2), "=r"(r3) : "r"(a))

#define MMA16816(d, a, b) \
    asm volatile("mma.sync.aligned.m16n8k16.row.col.f32.f16.f16.f32 " \
        "{%0,%1,%2,%3}, {%4,%5,%6,%7}, {%8,%9}, {%0,%1,%2,%3};" \
        : "+f"((d)[0]), "+f"((d)[1]), "+f"((d)[2]), "+f"((d)[3]) \
        : "r"((a)[0]), "r"((a)[1]), "r"((a)[2]), "r"((a)[3]), \
          "r"((b)[0]), "r"((b)[1]))

// ============================================================================
// fp32 -> fp16 convert
// ============================================================================
__global__ __launch_bounds__(256)
void cvt_fp16(const float* __restrict__ src, __half* __restrict__ dst, int n)
{
    const int i = (blockIdx.x * 256 + threadIdx.x) * 4;
    if (i < n) {
        const float4 v = *(const float4*)(src + i);
        *(__half2*)(dst + i)     = __floats2half2_rn(v.x, v.y);
        *(__half2*)(dst + i + 2) = __floats2half2_rn(v.z, v.w);
    }
}

// ============================================================================
// fp16 GEMM: C[16384 x 512] = Ah @ Wh^T + bias0 + bias1  (unchanged from R7;
// fragment layouts verified against PTX spec: ldmatrix x4 -> a0..a3 / b0,b1)
// ============================================================================
#define GSTAGE 32768
#define GNIT   (D_ / 64)    // 32

__global__ __launch_bounds__(256)
void gemm_h(const __half* __restrict__ Ah, const __half* __restrict__ Wh,
            const float* __restrict__ bias0, const float* __restrict__ bias1,
            float* __restrict__ C)
{
    __shared__ float sb[128];
    char* sm = (char*)dynsmem;
    const uint32_t smu = smem_u32(sm);

    const int tid  = threadIdx.x;
    const int wid  = tid >> 5, lane = tid & 31;
    const int wm   = wid & 3,  wn   = wid >> 2;
    const int g    = lane >> 2, tg  = lane & 3;
    const int n0   = blockIdx.x * 128;
    const int m0   = blockIdx.y * 128;

    if (tid < 128) sb[tid] = bias0[n0 + tid] + bias1[n0 + tid];

    const int arow  = wm * 32 + (lane & 15);
    const int acsel = (lane & 16) ? 16 : 0;
    const int brow  = wn * 64 + (lane & 7) + ((lane & 16) ? 8 : 0);
    const int bcsel = (lane & 8) ? 16 : 0;

    const __half* Ab = Ah + (long)m0 * D_;
    const __half* Wb = Wh + (long)n0 * D_;

    float acc[2][8][4];
    #pragma unroll
    for (int i = 0; i < 2; i++)
        #pragma unroll
        for (int j = 0; j < 8; j++)
            #pragma unroll
            for (int r = 0; r < 4; r++) acc[i][j][r] = 0.0f;

    uint4 ra[4], rb[4];

    #pragma unroll
    for (int i = 0; i < 4; i++) {
        const int f = tid + (i << 8), r = f >> 3, c8 = f & 7;
        ra[i] = *(const uint4*)(Ab + (long)r * D_ + c8 * 8);
        rb[i] = *(const uint4*)(Wb + (long)r * D_ + c8 * 8);
    }
    #pragma unroll
    for (int i = 0; i < 4; i++) {
        const int f = tid + (i << 8), r = f >> 3, c8 = f & 7;
        const uint32_t off = SWZ128(r * 128 + c8 * 16);
        *(uint4*)(sm + off)         = ra[i];
        *(uint4*)(sm + 16384 + off) = rb[i];
    }
    __syncthreads();

    for (int it = 0; it < GNIT; it++) {
        const int cur = it & 1;

        if (it + 1 < GNIT) {
            const long k = (long)(it + 1) * 64;
            #pragma unroll
            for (int i = 0; i < 4; i++) {
                const int f = tid + (i << 8), r = f >> 3, c8 = f & 7;
                ra[i] = *(const uint4*)(Ab + (long)r * D_ + k + c8 * 8);
                rb[i] = *(const uint4*)(Wb + (long)r * D_ + k + c8 * 8);
            }
        }

        const uint32_t a_st = smu + cur * GSTAGE;
        const uint32_t b_st = a_st + 16384;
        #pragma unroll
        for (int kk = 0; kk < 4; kk++) {
            uint32_t af[2][4], bf[8][2];
            #pragma unroll
            for (int mf = 0; mf < 2; mf++) {
                const uint32_t off =
                    SWZ128((arow + mf * 16) * 128 + kk * 32 + acsel);
                LDSM_X4(af[mf][0], af[mf][1], af[mf][2], af[mf][3], a_st + off);
            }
            #pragma unroll
            for (int np = 0; np < 4; np++) {
                const uint32_t off =
                    SWZ128((brow + np * 16) * 128 + kk * 32 + bcsel);
                uint32_t r0, r1, r2, r3;
                LDSM_X4(r0, r1, r2, r3, b_st + off);
                bf[2 * np][0] = r0;     bf[2 * np][1] = r1;
                bf[2 * np + 1][0] = r2; bf[2 * np + 1][1] = r3;
            }
            #pragma unroll
            for (int mf = 0; mf < 2; mf++)
                #pragma unroll
                for (int nf = 0; nf < 8; nf++)
                    MMA16816(acc[mf][nf], af[mf], bf[nf]);
        }

        if (it + 1 < GNIT) {
            char* ps = sm + ((it + 1) & 1) * GSTAGE;
            #pragma unroll
            for (int i = 0; i < 4; i++) {
                const int f = tid + (i << 8), r = f >> 3, c8 = f & 7;
                const uint32_t off = SWZ128(r * 128 + c8 * 16);
                *(uint4*)(ps + off)         = ra[i];
                *(uint4*)(ps + 16384 + off) = rb[i];
            }
        }
        __syncthreads();
    }

    #pragma unroll
    for (int mf = 0; mf < 2; mf++) {
        #pragma unroll
        for (int nf = 0; nf < 8; nf++) {
            const int cl  = wn * 64 + nf * 8 + 2 * tg;
            const float b0v = sb[cl], b1v = sb[cl + 1];
            const int r0 = m0 + wm * 32 + mf * 16 + g;
            float2 v0; v0.x = acc[mf][nf][0] + b0v; v0.y = acc[mf][nf][1] + b1v;
            *(float2*)(C + (long)r0 * G_ + n0 + cl) = v0;
            float2 v1; v1.x = acc[mf][nf][2] + b0v; v1.y = acc[mf][nf][3] + b1v;
            *(float2*)(C + (long)(r0 + 8) * G_ + n0 + cl) = v1;
        }
    }
}

// ============================================================================
// Forward LSTM recurrence v4 (FIXED row mapping): one CTA/batch, 512 threads,
// ONE THREAD PER GATE ROW (tid = row, covers all 512 rows).
// W row k in [0,80): 40 f32x2 registers. k in [80,128): smem, TRANSPOSED
// layout [chunk j][row] (32 lanes -> 512 contiguous bytes, conflict-free).
// h read as 32 broadcast LDS.128. All dot-product math fma.rn.f32x2.
// ============================================================================
#define WTAIL_CH 12                       // 12 float4 chunks = 48 floats
#define LSTM_SMEM ((128 + 512) * 4 + WTAIL_CH * 512 * 16)   // 100,864 B

__global__ __launch_bounds__(512)
void lstm_fwd4(const float* __restrict__ xp, const float* __restrict__ Whh,
               float* __restrict__ last)
{
    float*      h_s    = (float*)dynsmem;              // [128]
    float*      gate_s = h_s + 128;                    // [512]
    ulonglong2* Wt     = (ulonglong2*)(gate_s + 512);  // [12][512] 16B chunks

    const int tid = threadIdx.x;        // == gate row
    const int b   = blockIdx.x;

    // stage W tail (k in [80,128)) transposed: Wt[j][row]
    #pragma unroll
    for (int j = 0; j < WTAIL_CH; j++)
        Wt[j * 512 + tid] = *(const ulonglong2*)(Whh + tid * 128 + 80 + 4 * j);

    // W head (k in [0,80)) into 40 packed registers
    ull w[40];
    {
        const ull* wr = (const ull*)(Whh + tid * 128);
        #pragma unroll
        for (int i = 0; i < 40; i++) w[i] = wr[i];
    }
    if (tid < 128) h_s[tid] = 0.0f;
    float c = 0.0f;
    __syncthreads();

    const float* xprow = xp + (long)b * T_ * G_ + tid;
    float xv = xprow[0];

    for (int t = 0; t < T_; t++) {
        const ulonglong2* hp = (const ulonglong2*)h_s;   // broadcast reads
        ull a0 = 0, a1 = 0, a2 = 0, a3 = 0;
        #pragma unroll
        for (int i = 0; i < 20; i++) {                   // k 0..79 (registers)
            const ulonglong2 hv = hp[i];
            fma2(a0, w[2 * i],     hv.x);
            fma2(a1, w[2 * i + 1], hv.y);
        }
        #pragma unroll
        for (int j = 0; j < WTAIL_CH; j++) {             // k 80..127 (smem)
            const ulonglong2 wv = Wt[j * 512 + tid];
            const ulonglong2 hv = hp[20 + j];
            fma2(a2, wv.x, hv.x);
            fma2(a3, wv.y, hv.y);
        }
        const float2 f0 = unpk(a0), f1 = unpk(a1);
        const float2 f2v = unpk(a2), f3 = unpk(a3);
        const float s = ((f0.x + f0.y) + (f1.x + f1.y))
                      + ((f2v.x + f2v.y) + (f3.x + f3.y));
        gate_s[tid] = s + xv;
        if (t + 1 < T_) xv = xprow[(long)(t + 1) * G_];   // prefetch
        __syncthreads();
        if (tid < 128) {
            const float gi = gate_s[tid],       gf = gate_s[128 + tid];
            const float gg = gate_s[256 + tid], go = gate_s[384 + tid];
            c = fsig(gf) * c + fsig(gi) * ftanh(gg);
            const float h = fsig(go) * ftanh(c);
            h_s[tid] = h;
            if (t == T_ - 1) last[b * (2 * H_) + tid] = h;
        }
        __syncthreads();
    }
}

// ============================================================================
// Backward direction: ONE step from zero state (reverse-scan output at T-1).
// Rows needed: i (0..127), g (256..383), o (384..511).
// ============================================================================
__global__ __launch_bounds__(384)
void bwd_fused(const float* __restrict__ x, const float* __restrict__ Wihb,
               const float* __restrict__ bihb, const float* __restrict__ bhhb,
               float* __restrict__ last)
{
    __shared__ float xs[2048];
    __shared__ float gs[384];
    const int b = blockIdx.x, tid = threadIdx.x;

    const float* xr = x + ((long)b * T_ + (T_ - 1)) * D_;
    for (int i = tid; i < 2048; i += 384) xs[i] = xr[i];
    __syncthreads();

    const int r = (tid < 128) ? tid : (128 + tid);   // i rows, then g|o rows
    const float* wr = Wihb + (long)r * D_;
    float s = bihb[r] + bhhb[r];
    #pragma unroll 8
    for (int k = 0; k < 2048; k++) s = fmaf(wr[k], xs[k], s);
    gs[tid] = s;
    __syncthreads();

    if (tid < 128) {
        const float ci = fsig(gs[tid]) * ftanh(gs[128 + tid]);
        last[b * (2 * H_) + H_ + tid] = fsig(gs[256 + tid]) * ftanh(ci);
    }
}

// ============================================================================
// MLP head + softmax.
// ============================================================================
__global__ void head_kernel(const float* __restrict__ last,
                            const float* __restrict__ W1, const float* __restrict__ b1,
                            const float* __restrict__ W2, const float* __restrict__ b2,
                            const float* __restrict__ W3, const float* __restrict__ b3,
                            float* __restrict__ out)
{
    __shared__ float v[256], u[256], w2s[64], lg[11];
    const int b = blockIdx.x, tid = threadIdx.x;

    v[tid] = last[b * 256 + tid];
    __syncthreads();

    float a = b1[tid];
    #pragma unroll 8
    for (int k = 0; k < 256; k++) a = fmaf(W1[tid * 256 + k], v[k], a);
    u[tid] = a;
    __syncthreads();

    if (tid < 64) {
        float s = b2[tid];
        #pragma unroll 8
        for (int k = 0; k < 256; k++) s = fmaf(W2[tid * 256 + k], u[k], s);
        w2s[tid] = s;
    }
    __syncthreads();

    if (tid < 11) {
        float s = b3[tid];
        #pragma unroll
        for (int k = 0; k < 64; k++) s = fmaf(W3[tid * 64 + k], w2s[k], s);
        lg[tid] = s;
    }
    __syncthreads();

    if (tid == 0) {
        float mx = lg[0];
        for (int i = 1; i < 11; i++) mx = fmaxf(mx, lg[i]);
        float e[11], sum = 0.0f;
        for (int i = 0; i < 11; i++) { e[i] = expf(lg[i] - mx); sum += e[i]; }
        const float inv = 1.0f / sum;
        for (int i = 0; i < 11; i++) out[b * 11 + i] = e[i] * inv;
    }
}

// ============================================================================
extern "C" void kernel_launch(void* const* d_in, const int* in_sizes, int n_in,
                              void* d_out, int out_size)
{
    const float* x    = (const float*)d_in[0];
    const float* Wihf = (const float*)d_in[1];
    const float* Whhf = (const float*)d_in[2];
    const float* bihf = (const float*)d_in[3];
    const float* bhhf = (const float*)d_in[4];
    const float* Wihb = (const float*)d_in[5];
    const float* bihb = (const float*)d_in[7];
    const float* bhhb = (const float*)d_in[8];
    const float* W1 = (const float*)d_in[9];   const float* b1 = (const float*)d_in[10];
    const float* W2 = (const float*)d_in[11];  const float* b2 = (const float*)d_in[12];
    const float* W3 = (const float*)d_in[13];  const float* b3 = (const float*)d_in[14];
    float* out = (float*)d_out;

    void* p;
    cudaGetSymbolAddress(&p, g_xp);   float*  xp   = (float*)p;
    cudaGetSymbolAddress(&p, g_last); float*  last = (float*)p;
    cudaGetSymbolAddress(&p, g_Ah);   __half* Ah   = (__half*)p;
    cudaGetSymbolAddress(&p, g_Wh);   __half* Wh   = (__half*)p;

    const int gemm_smem = 2 * GSTAGE;   // 64 KB
    cudaFuncSetAttribute(gemm_h,    cudaFuncAttributeMaxDynamicSharedMemorySize, gemm_smem);
    cudaFuncSetAttribute(lstm_fwd4, cudaFuncAttributeMaxDynamicSharedMemorySize, LSTM_SMEM);

    cvt_fp16<<<(M_FWD * D_) / 1024, 256>>>(x,    Ah, M_FWD * D_);
    cvt_fp16<<<(G_ * D_) / 1024,    256>>>(Wihf, Wh, G_ * D_);

    gemm_h<<<dim3(G_ / 128, M_FWD / 128), 256, gemm_smem>>>(Ah, Wh, bihf, bhhf, xp);

    bwd_fused<<<B_, 384>>>(x, Wihb, bihb, bhhb, last);

    lstm_fwd4<<<B_, 512, LSTM_SMEM>>>(xp, Whhf, last);

    head_kernel<<<B_, 256>>>(last, W1, b1, W2, b2, W3, b3, out);
}

// round 9
// speedup vs baseline: 2.9495x; 1.5867x over previous
#include <cuda_runtime.h>
#include <cuda_fp16.h>
#include <cstdint>

#define B_  32
#define T_  512
#define D_  2048
#define H_  128
#define G_  512
#define M_FWD (B_ * T_)

typedef unsigned long long ull;

__device__ float  g_xp[M_FWD * G_];       // forward gate preacts [B*T, 4H]
__device__ float  g_last[B_ * 2 * H_];    // [h_fwd | h_bwd]
__device__ __half g_Ah[M_FWD * D_];       // fp16 copy of inputs
__device__ __half g_Wh[G_ * D_];          // fp16 copy of W_ih_f

extern __shared__ unsigned char dynsmem[];

// ---------------- helpers ---------------------------------------------------
__device__ __forceinline__ uint32_t smem_u32(const void* p) {
    uint32_t a;
    asm("{ .reg .u64 t; cvta.to.shared.u64 t, %1; cvt.u32.u64 %0, t; }"
        : "=r"(a) : "l"(p));
    return a;
}
__device__ __forceinline__ void fma2(ull& d, ull a, ull b) {
    asm("fma.rn.f32x2 %0, %1, %2, %0;" : "+l"(d) : "l"(a), "l"(b));
}
__device__ __forceinline__ float2 unpk(ull v) {
    float2 r; asm("mov.b64 {%0,%1}, %2;" : "=f"(r.x), "=f"(r.y) : "l"(v)); return r;
}
__device__ __forceinline__ ull pk2(float2 v) {
    ull r; asm("mov.b64 %0, {%1,%2};" : "=l"(r) : "f"(v.x), "f"(v.y)); return r;
}
// exact activations (match reference; R6 showed approx variants are unusable)
__device__ __forceinline__ float fsig(float x)  { return 1.0f / (1.0f + expf(-x)); }
__device__ __forceinline__ float ftanh(float x) { return tanhf(x); }

#define SWZ128(o) ((o) ^ (((o) >> 3) & 0x70))

#define LDSM_X4(r0, r1, r2, r3, a) \
    asm volatile("ldmatrix.sync.aligned.m8n8.x4.shared.b16 {%0,%1,%2,%3}, [%4];" \
                 : "=r"(r0), "=r"(r1), "=r"(r2), "=r"(r3) : "r"(a))

#define MMA16816(d, a, b) \
    asm volatile("mma.sync.aligned.m16n8k16.row.col.f32.f16.f16.f32 " \
        "{%0,%1,%2,%3}, {%4,%5,%6,%7}, {%8,%9}, {%0,%1,%2,%3};" \
        : "+f"((d)[0]), "+f"((d)[1]), "+f"((d)[2]), "+f"((d)[3]) \
        : "r"((a)[0]), "r"((a)[1]), "r"((a)[2]), "r"((a)[3]), \
          "r"((b)[0]), "r"((b)[1]))

// ============================================================================
// fp32 -> fp16 convert
// ============================================================================
__global__ __launch_bounds__(256)
void cvt_fp16(const float* __restrict__ src, __half* __restrict__ dst, int n)
{
    const int i = (blockIdx.x * 256 + threadIdx.x) * 4;
    if (i < n) {
        const float4 v = *(const float4*)(src + i);
        *(__half2*)(dst + i)     = __floats2half2_rn(v.x, v.y);
        *(__half2*)(dst + i + 2) = __floats2half2_rn(v.z, v.w);
    }
}

// ============================================================================
// fp16 GEMM: C[16384 x 512] = Ah @ Wh^T + bias0 + bias1  (unchanged from R8)
// ============================================================================
#define GSTAGE 32768
#define GNIT   (D_ / 64)    // 32

__global__ __launch_bounds__(256)
void gemm_h(const __half* __restrict__ Ah, const __half* __restrict__ Wh,
            const float* __restrict__ bias0, const float* __restrict__ bias1,
            float* __restrict__ C)
{
    __shared__ float sb[128];
    char* sm = (char*)dynsmem;
    const uint32_t smu = smem_u32(sm);

    const int tid  = threadIdx.x;
    const int wid  = tid >> 5, lane = tid & 31;
    const int wm   = wid & 3,  wn   = wid >> 2;
    const int g    = lane >> 2, tg  = lane & 3;
    const int n0   = blockIdx.x * 128;
    const int m0   = blockIdx.y * 128;

    if (tid < 128) sb[tid] = bias0[n0 + tid] + bias1[n0 + tid];

    const int arow  = wm * 32 + (lane & 15);
    const int acsel = (lane & 16) ? 16 : 0;
    const int brow  = wn * 64 + (lane & 7) + ((lane & 16) ? 8 : 0);
    const int bcsel = (lane & 8) ? 16 : 0;

    const __half* Ab = Ah + (long)m0 * D_;
    const __half* Wb = Wh + (long)n0 * D_;

    float acc[2][8][4];
    #pragma unroll
    for (int i = 0; i < 2; i++)
        #pragma unroll
        for (int j = 0; j < 8; j++)
            #pragma unroll
            for (int r = 0; r < 4; r++) acc[i][j][r] = 0.0f;

    uint4 ra[4], rb[4];

    #pragma unroll
    for (int i = 0; i < 4; i++) {
        const int f = tid + (i << 8), r = f >> 3, c8 = f & 7;
        ra[i] = *(const uint4*)(Ab + (long)r * D_ + c8 * 8);
        rb[i] = *(const uint4*)(Wb + (long)r * D_ + c8 * 8);
    }
    #pragma unroll
    for (int i = 0; i < 4; i++) {
        const int f = tid + (i << 8), r = f >> 3, c8 = f & 7;
        const uint32_t off = SWZ128(r * 128 + c8 * 16);
        *(uint4*)(sm + off)         = ra[i];
        *(uint4*)(sm + 16384 + off) = rb[i];
    }
    __syncthreads();

    for (int it = 0; it < GNIT; it++) {
        const int cur = it & 1;

        if (it + 1 < GNIT) {
            const long k = (long)(it + 1) * 64;
            #pragma unroll
            for (int i = 0; i < 4; i++) {
                const int f = tid + (i << 8), r = f >> 3, c8 = f & 7;
                ra[i] = *(const uint4*)(Ab + (long)r * D_ + k + c8 * 8);
                rb[i] = *(const uint4*)(Wb + (long)r * D_ + k + c8 * 8);
            }
        }

        const uint32_t a_st = smu + cur * GSTAGE;
        const uint32_t b_st = a_st + 16384;
        #pragma unroll
        for (int kk = 0; kk < 4; kk++) {
            uint32_t af[2][4], bf[8][2];
            #pragma unroll
            for (int mf = 0; mf < 2; mf++) {
                const uint32_t off =
                    SWZ128((arow + mf * 16) * 128 + kk * 32 + acsel);
                LDSM_X4(af[mf][0], af[mf][1], af[mf][2], af[mf][3], a_st + off);
            }
            #pragma unroll
            for (int np = 0; np < 4; np++) {
                const uint32_t off =
                    SWZ128((brow + np * 16) * 128 + kk * 32 + bcsel);
                uint32_t r0, r1, r2, r3;
                LDSM_X4(r0, r1, r2, r3, b_st + off);
                bf[2 * np][0] = r0;     bf[2 * np][1] = r1;
                bf[2 * np + 1][0] = r2; bf[2 * np + 1][1] = r3;
            }
            #pragma unroll
            for (int mf = 0; mf < 2; mf++)
                #pragma unroll
                for (int nf = 0; nf < 8; nf++)
                    MMA16816(acc[mf][nf], af[mf], bf[nf]);
        }

        if (it + 1 < GNIT) {
            char* ps = sm + ((it + 1) & 1) * GSTAGE;
            #pragma unroll
            for (int i = 0; i < 4; i++) {
                const int f = tid + (i << 8), r = f >> 3, c8 = f & 7;
                const uint32_t off = SWZ128(r * 128 + c8 * 16);
                *(uint4*)(ps + off)         = ra[i];
                *(uint4*)(ps + 16384 + off) = rb[i];
            }
        }
        __syncthreads();
    }

    #pragma unroll
    for (int mf = 0; mf < 2; mf++) {
        #pragma unroll
        for (int nf = 0; nf < 8; nf++) {
            const int cl  = wn * 64 + nf * 8 + 2 * tg;
            const float b0v = sb[cl], b1v = sb[cl + 1];
            const int r0 = m0 + wm * 32 + mf * 16 + g;
            float2 v0; v0.x = acc[mf][nf][0] + b0v; v0.y = acc[mf][nf][1] + b1v;
            *(float2*)(C + (long)r0 * G_ + n0 + cl) = v0;
            float2 v1; v1.x = acc[mf][nf][2] + b0v; v1.y = acc[mf][nf][3] + b1v;
            *(float2*)(C + (long)(r0 + 8) * G_ + n0 + cl) = v1;
        }
    }
}

// ============================================================================
// Forward LSTM recurrence v5: one CTA/batch, 512 threads, ONE THREAD PER GATE
// ROW. W row k in [0,80): 40 f32x2 registers. k in [80,128): smem as fp16,
// transposed [chunk][row] (halves crossbar traffic vs fp32 tail).
// Each thread applies its own gate activation BEFORE the barrier (spreads
// MUFU/expf work over 512 threads and shortens the serial pointwise tail).
// ============================================================================
#define WTAIL_CH 12                       // 12 chunks x 4 halves = 48 floats
#define LSTM_SMEM ((128 + 512) * 4 + WTAIL_CH * 512 * 8)   // 51,712 B

__global__ __launch_bounds__(512)
void lstm_fwd5(const float* __restrict__ xp, const float* __restrict__ Whh,
               float* __restrict__ last)
{
    float* h_s    = (float*)dynsmem;               // [128]
    float* gate_s = h_s + 128;                     // [512] (activated gates)
    ull*   Wt     = (ull*)(gate_s + 512);          // [12][512], 4 halves each

    const int tid = threadIdx.x;        // == gate row
    const int b   = blockIdx.x;
    const bool is_g = (tid >= 256) && (tid < 384);

    // stage W tail (k in [80,128)) transposed + fp16: Wt[j][row]
    #pragma unroll
    for (int j = 0; j < WTAIL_CH; j++) {
        const float4 wv = *(const float4*)(Whh + tid * 128 + 80 + 4 * j);
        uint2 u;
        *(__half2*)&u.x = __floats2half2_rn(wv.x, wv.y);
        *(__half2*)&u.y = __floats2half2_rn(wv.z, wv.w);
        Wt[j * 512 + tid] = *(ull*)&u;
    }
    // W head (k in [0,80)) into 40 packed registers
    ull w[40];
    {
        const ull* wr = (const ull*)(Whh + tid * 128);
        #pragma unroll
        for (int i = 0; i < 40; i++) w[i] = wr[i];
    }
    if (tid < 128) h_s[tid] = 0.0f;
    float c = 0.0f;
    __syncthreads();

    const float* xprow = xp + (long)b * T_ * G_ + tid;
    float xv = xprow[0];

    for (int t = 0; t < T_; t++) {
        const ulonglong2* hp = (const ulonglong2*)h_s;   // broadcast reads
        ull a0 = 0, a1 = 0, a2 = 0, a3 = 0;
        #pragma unroll
        for (int i = 0; i < 20; i++) {                   // k 0..79 (registers)
            const ulonglong2 hv = hp[i];
            fma2(a0, w[2 * i],     hv.x);
            fma2(a1, w[2 * i + 1], hv.y);
        }
        #pragma unroll
        for (int j = 0; j < WTAIL_CH; j++) {             // k 80..127 (fp16 smem)
            const ull wv = Wt[j * 512 + tid];
            const uint2 u = *(const uint2*)&wv;
            const ulonglong2 hv = hp[20 + j];
            fma2(a2, pk2(__half22float2(*(const __half2*)&u.x)), hv.x);
            fma2(a3, pk2(__half22float2(*(const __half2*)&u.y)), hv.y);
        }
        const float2 f0 = unpk(a0), f1 = unpk(a1);
        const float2 f2v = unpk(a2), f3 = unpk(a3);
        const float pre = xv + ((f0.x + f0.y) + (f1.x + f1.y))
                             + ((f2v.x + f2v.y) + (f3.x + f3.y));
        // per-row activation, spread over all 512 threads
        gate_s[tid] = is_g ? ftanh(pre) : fsig(pre);
        if (t + 1 < T_) xv = xprow[(long)(t + 1) * G_];   // prefetch
        __syncthreads();
        if (tid < 128) {
            const float ai = gate_s[tid],       af = gate_s[128 + tid];
            const float ag = gate_s[256 + tid], ao = gate_s[384 + tid];
            c = af * c + ai * ag;
            const float h = ao * ftanh(c);
            h_s[tid] = h;
            if (t == T_ - 1) last[b * (2 * H_) + tid] = h;
        }
        __syncthreads();
    }
}

// ============================================================================
// Backward direction v2: ONE step from zero state (reverse-scan output at
// T-1). One CTA per batch, 1024 threads = 32 warps; each warp computes 12 of
// the 384 needed gate rows (i: 0..127, g: 256..383, o: 384..511) with
// lane-split k (16 coalesced float4 per lane) + shfl reduction.
// ============================================================================
__global__ __launch_bounds__(1024)
void bwd_fused(const float* __restrict__ x, const float* __restrict__ Wihb,
               const float* __restrict__ bihb, const float* __restrict__ bhhb,
               float* __restrict__ last)
{
    __shared__ float xs[2048];
    __shared__ float gs[384];
    const int b = blockIdx.x, tid = threadIdx.x;
    const int warp = tid >> 5, lane = tid & 31;

    const float* xr = x + ((long)b * T_ + (T_ - 1)) * D_;
    for (int i = tid; i < 2048; i += 1024) xs[i] = xr[i];
    __syncthreads();

    #pragma unroll
    for (int jj = 0; jj < 12; jj++) {
        const int j = warp * 12 + jj;                 // 0..383
        const int r = (j < 128) ? j : (j + 128);      // skip f rows
        const float4* wr = (const float4*)(Wihb + (long)r * D_);
        float s = 0.0f;
        #pragma unroll
        for (int it = 0; it < 16; it++) {
            const float4 wv = wr[it * 32 + lane];
            const float4 hx = *(const float4*)(xs + 4 * (it * 32 + lane));
            s += wv.x * hx.x + wv.y * hx.y + wv.z * hx.z + wv.w * hx.w;
        }
        #pragma unroll
        for (int d = 16; d > 0; d >>= 1)
            s += __shfl_xor_sync(0xFFFFFFFFu, s, d);
        if (lane == 0) gs[j] = s + bihb[r] + bhhb[r];
    }
    __syncthreads();

    if (tid < 128) {
        const float ci = fsig(gs[tid]) * ftanh(gs[128 + tid]);
        last[b * (2 * H_) + H_ + tid] = fsig(gs[256 + tid]) * ftanh(ci);
    }
}

// ============================================================================
// MLP head + softmax.
// ============================================================================
__global__ void head_kernel(const float* __restrict__ last,
                            const float* __restrict__ W1, const float* __restrict__ b1,
                            const float* __restrict__ W2, const float* __restrict__ b2,
                            const float* __restrict__ W3, const float* __restrict__ b3,
                            float* __restrict__ out)
{
    __shared__ float v[256], u[256], w2s[64], lg[11];
    const int b = blockIdx.x, tid = threadIdx.x;

    v[tid] = last[b * 256 + tid];
    __syncthreads();

    float a = b1[tid];
    #pragma unroll 8
    for (int k = 0; k < 256; k++) a = fmaf(W1[tid * 256 + k], v[k], a);
    u[tid] = a;
    __syncthreads();

    if (tid < 64) {
        float s = b2[tid];
        #pragma unroll 8
        for (int k = 0; k < 256; k++) s = fmaf(W2[tid * 256 + k], u[k], s);
        w2s[tid] = s;
    }
    __syncthreads();

    if (tid < 11) {
        float s = b3[tid];
        #pragma unroll
        for (int k = 0; k < 64; k++) s = fmaf(W3[tid * 64 + k], w2s[k], s);
        lg[tid] = s;
    }
    __syncthreads();

    if (tid == 0) {
        float mx = lg[0];
        for (int i = 1; i < 11; i++) mx = fmaxf(mx, lg[i]);
        float e[11], sum = 0.0f;
        for (int i = 0; i < 11; i++) { e[i] = expf(lg[i] - mx); sum += e[i]; }
        const float inv = 1.0f / sum;
        for (int i = 0; i < 11; i++) out[b * 11 + i] = e[i] * inv;
    }
}

// ============================================================================
extern "C" void kernel_launch(void* const* d_in, const int* in_sizes, int n_in,
                              void* d_out, int out_size)
{
    const float* x    = (const float*)d_in[0];
    const float* Wihf = (const float*)d_in[1];
    const float* Whhf = (const float*)d_in[2];
    const float* bihf = (const float*)d_in[3];
    const float* bhhf = (const float*)d_in[4];
    const float* Wihb = (const float*)d_in[5];
    const float* bihb = (const float*)d_in[7];
    const float* bhhb = (const float*)d_in[8];
    const float* W1 = (const float*)d_in[9];   const float* b1 = (const float*)d_in[10];
    const float* W2 = (const float*)d_in[11];  const float* b2 = (const float*)d_in[12];
    const float* W3 = (const float*)d_in[13];  const float* b3 = (const float*)d_in[14];
    float* out = (float*)d_out;

    void* p;
    cudaGetSymbolAddress(&p, g_xp);   float*  xp   = (float*)p;
    cudaGetSymbolAddress(&p, g_last); float*  last = (float*)p;
    cudaGetSymbolAddress(&p, g_Ah);   __half* Ah   = (__half*)p;
    cudaGetSymbolAddress(&p, g_Wh);   __half* Wh   = (__half*)p;

    const int gemm_smem = 2 * GSTAGE;   // 64 KB
    cudaFuncSetAttribute(gemm_h,    cudaFuncAttributeMaxDynamicSharedMemorySize, gemm_smem);
    cudaFuncSetAttribute(lstm_fwd5, cudaFuncAttributeMaxDynamicSharedMemorySize, LSTM_SMEM);

    cvt_fp16<<<(M_FWD * D_) / 1024, 256>>>(x,    Ah, M_FWD * D_);
    cvt_fp16<<<(G_ * D_) / 1024,    256>>>(Wihf, Wh, G_ * D_);

    gemm_h<<<dim3(G_ / 128, M_FWD / 128), 256, gemm_smem>>>(Ah, Wh, bihf, bhhf, xp);

    bwd_fused<<<B_, 1024>>>(x, Wihb, bihb, bhhb, last);

    lstm_fwd5<<<B_, 512, LSTM_SMEM>>>(xp, Whhf, last);

    head_kernel<<<B_, 256>>>(last, W1, b1, W2, b2, W3, b3, out);
}

// round 10
// speedup vs baseline: 3.2324x; 1.0959x over previous
#include <cuda_runtime.h>
#include <cuda_fp16.h>
#include <cstdint>

#define B_  32
#define T_  512
#define D_  2048
#define H_  128
#define G_  512
#define M_FWD (B_ * T_)

typedef unsigned long long ull;

__device__ float  g_xp[M_FWD * G_];       // forward gate preacts [B*T, 4H]
__device__ float  g_last[B_ * 2 * H_];    // [h_fwd | h_bwd]
__device__ float  g_gb[B_ * 384];         // backward gate preacts (i|g|o rows)
__device__ __half g_Ah[M_FWD * D_];       // fp16 copy of inputs
__device__ __half g_Wh[G_ * D_];          // fp16 copy of W_ih_f

extern __shared__ unsigned char dynsmem[];

// ---------------- helpers ---------------------------------------------------
__device__ __forceinline__ uint32_t smem_u32(const void* p) {
    uint32_t a;
    asm("{ .reg .u64 t; cvta.to.shared.u64 t, %1; cvt.u32.u64 %0, t; }"
        : "=r"(a) : "l"(p));
    return a;
}
__device__ __forceinline__ void fma2(ull& d, ull a, ull b) {
    asm("fma.rn.f32x2 %0, %1, %2, %0;" : "+l"(d) : "l"(a), "l"(b));
}
__device__ __forceinline__ float2 unpk(ull v) {
    float2 r; asm("mov.b64 {%0,%1}, %2;" : "=f"(r.x), "=f"(r.y) : "l"(v)); return r;
}
__device__ __forceinline__ ull pk2(float2 v) {
    ull r; asm("mov.b64 %0, {%1,%2};" : "=l"(r) : "f"(v.x), "f"(v.y)); return r;
}
// exact activations (match reference; approx variants fail the 1e-3 bar)
__device__ __forceinline__ float fsig(float x)  { return 1.0f / (1.0f + expf(-x)); }
__device__ __forceinline__ float ftanh(float x) { return tanhf(x); }

#define SWZ128(o) ((o) ^ (((o) >> 3) & 0x70))

#define LDSM_X4(r0, r1, r2, r3, a) \
    asm volatile("ldmatrix.sync.aligned.m8n8.x4.shared.b16 {%0,%1,%2,%3}, [%4];" \
                 : "=r"(r0), "=r"(r1), "=r"(r2), "=r"(r3) : "r"(a))

#define MMA16816(d, a, b) \
    asm volatile("mma.sync.aligned.m16n8k16.row.col.f32.f16.f16.f32 " \
        "{%0,%1,%2,%3}, {%4,%5,%6,%7}, {%8,%9}, {%0,%1,%2,%3};" \
        : "+f"((d)[0]), "+f"((d)[1]), "+f"((d)[2]), "+f"((d)[3]) \
        : "r"((a)[0]), "r"((a)[1]), "r"((a)[2]), "r"((a)[3]), \
          "r"((b)[0]), "r"((b)[1]))

#define CP_ASYNC16(sa, gp) \
    asm volatile("cp.async.ca.shared.global [%0], [%1], 16;" \
                 :: "r"(sa), "l"(gp) : "memory")
#define CP_COMMIT()  asm volatile("cp.async.commit_group;" ::: "memory")
#define CP_WAIT(n)   asm volatile("cp.async.wait_group %0;" :: "n"(n) : "memory")

// ============================================================================
// fp32 -> fp16 convert
// ============================================================================
__global__ __launch_bounds__(256)
void cvt_fp16(const float* __restrict__ src, __half* __restrict__ dst, int n)
{
    const int i = (blockIdx.x * 256 + threadIdx.x) * 4;
    if (i < n) {
        const float4 v = *(const float4*)(src + i);
        *(__half2*)(dst + i)     = __floats2half2_rn(v.x, v.y);
        *(__half2*)(dst + i + 2) = __floats2half2_rn(v.z, v.w);
    }
}

// ============================================================================
// fp16 GEMM v2: C[16384 x 512] = Ah @ Wh^T + bias0 + bias1
// Same proven ldmatrix/mma core as R8/R9; staging rewritten as a 3-stage
// cp.async (LDGSTS) pipeline — one barrier per iter, LDG latency hidden by
// 2 tiles in flight instead of the sync-bound double buffer.
// ============================================================================
#define GSTAGE 32768
#define GNIT   (D_ / 64)    // 32

__global__ __launch_bounds__(256)
void gemm_h(const __half* __restrict__ Ah, const __half* __restrict__ Wh,
            const float* __restrict__ bias0, const float* __restrict__ bias1,
            float* __restrict__ C)
{
    __shared__ float sb[128];
    char* sm = (char*)dynsmem;                 // 3 x 32KB stages
    const uint32_t smu = smem_u32(sm);

    const int tid  = threadIdx.x;
    const int wid  = tid >> 5, lane = tid & 31;
    const int wm   = wid & 3,  wn   = wid >> 2;
    const int g    = lane >> 2, tg  = lane & 3;
    const int n0   = blockIdx.x * 128;
    const int m0   = blockIdx.y * 128;

    if (tid < 128) sb[tid] = bias0[n0 + tid] + bias1[n0 + tid];

    const int arow  = wm * 32 + (lane & 15);
    const int acsel = (lane & 16) ? 16 : 0;
    const int brow  = wn * 64 + (lane & 7) + ((lane & 16) ? 8 : 0);
    const int bcsel = (lane & 8) ? 16 : 0;

    const __half* Ab = Ah + (long)m0 * D_;
    const __half* Wb = Wh + (long)n0 * D_;

    // per-thread staging coords (4 x 16B for A, 4 x 16B for B per stage)
    const int sr0 = tid >> 3;          // row 0..31 (+32 per i)
    const int sc8 = tid & 7;           // 16B chunk within 128B row

    #define ISSUE_STAGE(s, kt) do {                                           \
        const uint32_t _st = smu + (s) * GSTAGE;                              \
        const long _k = (long)(kt) * 64;                                      \
        _Pragma("unroll")                                                     \
        for (int _i = 0; _i < 4; _i++) {                                      \
            const int _r = sr0 + _i * 32;                                     \
            const uint32_t _off = SWZ128(_r * 128 + sc8 * 16);                \
            CP_ASYNC16(_st + _off,         Ab + (long)_r * D_ + _k + sc8 * 8);\
            CP_ASYNC16(_st + 16384 + _off, Wb + (long)_r * D_ + _k + sc8 * 8);\
        }                                                                     \
    } while (0)

    ISSUE_STAGE(0, 0); CP_COMMIT();
    ISSUE_STAGE(1, 1); CP_COMMIT();

    float acc[2][8][4];
    #pragma unroll
    for (int i = 0; i < 2; i++)
        #pragma unroll
        for (int j = 0; j < 8; j++)
            #pragma unroll
            for (int r = 0; r < 4; r++) acc[i][j][r] = 0.0f;

    for (int it = 0; it < GNIT; it++) {
        if (it + 1 < GNIT) CP_WAIT(1); else CP_WAIT(0);
        __syncthreads();
        if (it + 2 < GNIT) { ISSUE_STAGE((it + 2) % 3, it + 2); CP_COMMIT(); }

        const uint32_t a_st = smu + (it % 3) * GSTAGE;
        const uint32_t b_st = a_st + 16384;
        #pragma unroll
        for (int kk = 0; kk < 4; kk++) {
            uint32_t af[2][4], bf[8][2];
            #pragma unroll
            for (int mf = 0; mf < 2; mf++) {
                const uint32_t off =
                    SWZ128((arow + mf * 16) * 128 + kk * 32 + acsel);
                LDSM_X4(af[mf][0], af[mf][1], af[mf][2], af[mf][3], a_st + off);
            }
            #pragma unroll
            for (int np = 0; np < 4; np++) {
                const uint32_t off =
                    SWZ128((brow + np * 16) * 128 + kk * 32 + bcsel);
                uint32_t r0, r1, r2, r3;
                LDSM_X4(r0, r1, r2, r3, b_st + off);
                bf[2 * np][0] = r0;     bf[2 * np][1] = r1;
                bf[2 * np + 1][0] = r2; bf[2 * np + 1][1] = r3;
            }
            #pragma unroll
            for (int mf = 0; mf < 2; mf++)
                #pragma unroll
                for (int nf = 0; nf < 8; nf++)
                    MMA16816(acc[mf][nf], af[mf], bf[nf]);
        }
    }

    #pragma unroll
    for (int mf = 0; mf < 2; mf++) {
        #pragma unroll
        for (int nf = 0; nf < 8; nf++) {
            const int cl  = wn * 64 + nf * 8 + 2 * tg;
            const float b0v = sb[cl], b1v = sb[cl + 1];
            const int r0 = m0 + wm * 32 + mf * 16 + g;
            float2 v0; v0.x = acc[mf][nf][0] + b0v; v0.y = acc[mf][nf][1] + b1v;
            *(float2*)(C + (long)r0 * G_ + n0 + cl) = v0;
            float2 v1; v1.x = acc[mf][nf][2] + b0v; v1.y = acc[mf][nf][3] + b1v;
            *(float2*)(C + (long)(r0 + 8) * G_ + n0 + cl) = v1;
        }
    }
}

// ============================================================================
// Forward LSTM recurrence v5 (unchanged from R9 — passing, near FMA floor).
// ============================================================================
#define WTAIL_CH 12
#define LSTM_SMEM ((128 + 512) * 4 + WTAIL_CH * 512 * 8)   // 51,712 B

__global__ __launch_bounds__(512)
void lstm_fwd5(const float* __restrict__ xp, const float* __restrict__ Whh,
               float* __restrict__ last)
{
    float* h_s    = (float*)dynsmem;               // [128]
    float* gate_s = h_s + 128;                     // [512] (activated gates)
    ull*   Wt     = (ull*)(gate_s + 512);          // [12][512], 4 halves each

    const int tid = threadIdx.x;        // == gate row
    const int b   = blockIdx.x;
    const bool is_g = (tid >= 256) && (tid < 384);

    #pragma unroll
    for (int j = 0; j < WTAIL_CH; j++) {
        const float4 wv = *(const float4*)(Whh + tid * 128 + 80 + 4 * j);
        uint2 u;
        *(__half2*)&u.x = __floats2half2_rn(wv.x, wv.y);
        *(__half2*)&u.y = __floats2half2_rn(wv.z, wv.w);
        Wt[j * 512 + tid] = *(ull*)&u;
    }
    ull w[40];
    {
        const ull* wr = (const ull*)(Whh + tid * 128);
        #pragma unroll
        for (int i = 0; i < 40; i++) w[i] = wr[i];
    }
    if (tid < 128) h_s[tid] = 0.0f;
    float c = 0.0f;
    __syncthreads();

    const float* xprow = xp + (long)b * T_ * G_ + tid;
    float xv = xprow[0];

    for (int t = 0; t < T_; t++) {
        const ulonglong2* hp = (const ulonglong2*)h_s;
        ull a0 = 0, a1 = 0, a2 = 0, a3 = 0;
        #pragma unroll
        for (int i = 0; i < 20; i++) {
            const ulonglong2 hv = hp[i];
            fma2(a0, w[2 * i],     hv.x);
            fma2(a1, w[2 * i + 1], hv.y);
        }
        #pragma unroll
        for (int j = 0; j < WTAIL_CH; j++) {
            const ull wv = Wt[j * 512 + tid];
            const uint2 u = *(const uint2*)&wv;
            const ulonglong2 hv = hp[20 + j];
            fma2(a2, pk2(__half22float2(*(const __half2*)&u.x)), hv.x);
            fma2(a3, pk2(__half22float2(*(const __half2*)&u.y)), hv.y);
        }
        const float2 f0 = unpk(a0), f1 = unpk(a1);
        const float2 f2v = unpk(a2), f3 = unpk(a3);
        const float pre = xv + ((f0.x + f0.y) + (f1.x + f1.y))
                             + ((f2v.x + f2v.y) + (f3.x + f3.y));
        gate_s[tid] = is_g ? ftanh(pre) : fsig(pre);
        if (t + 1 < T_) xv = xprow[(long)(t + 1) * G_];
        __syncthreads();
        if (tid < 128) {
            const float ai = gate_s[tid],       af = gate_s[128 + tid];
            const float ag = gate_s[256 + tid], ao = gate_s[384 + tid];
            c = af * c + ai * ag;
            const float h = ao * ftanh(c);
            h_s[tid] = h;
            if (t == T_ - 1) last[b * (2 * H_) + tid] = h;
        }
        __syncthreads();
    }
}

// ============================================================================
// Backward direction v3: ONE step from zero state, split over 128 CTAs.
// Grid (4 slices, 32 batches), 1024 threads = 32 warps; each warp computes 3
// of this slice's 96 gate rows (of the 384 needed: i 0..127, g 256..383,
// o 384..511) with lane-split k + shfl reduce. Pointwise in a second kernel.
// ============================================================================
__global__ __launch_bounds__(1024)
void bwd_gemm(const float* __restrict__ x, const float* __restrict__ Wihb,
              const float* __restrict__ bihb, const float* __restrict__ bhhb,
              float* __restrict__ gb)
{
    __shared__ float xs[2048];
    const int b = blockIdx.y, slice = blockIdx.x;
    const int tid = threadIdx.x, warp = tid >> 5, lane = tid & 31;

    const float* xr = x + ((long)b * T_ + (T_ - 1)) * D_;
    for (int i = tid; i < 2048; i += 1024) xs[i] = xr[i];
    __syncthreads();

    #pragma unroll
    for (int jj = 0; jj < 3; jj++) {
        const int j = slice * 96 + warp * 3 + jj;     // 0..383
        const int r = (j < 128) ? j : (j + 128);      // skip f rows
        const float4* wr = (const float4*)(Wihb + (long)r * D_);
        float s = 0.0f;
        #pragma unroll
        for (int it = 0; it < 16; it++) {
            const float4 wv = wr[it * 32 + lane];
            const float4 hx = *(const float4*)(xs + 4 * (it * 32 + lane));
            s += wv.x * hx.x + wv.y * hx.y + wv.z * hx.z + wv.w * hx.w;
        }
        #pragma unroll
        for (int d = 16; d > 0; d >>= 1)
            s += __shfl_xor_sync(0xFFFFFFFFu, s, d);
        if (lane == 0) gb[b * 384 + j] = s + bihb[r] + bhhb[r];
    }
}

__global__ void bwd_point(const float* __restrict__ gb, float* __restrict__ last)
{
    const int b = blockIdx.x, j = threadIdx.x;   // 32 x 128
    const float* r = gb + b * 384;
    const float ci = fsig(r[j]) * ftanh(r[128 + j]);
    last[b * (2 * H_) + H_ + j] = fsig(r[256 + j]) * ftanh(ci);
}

// ============================================================================
// MLP head + softmax.
// ============================================================================
__global__ void head_kernel(const float* __restrict__ last,
                            const float* __restrict__ W1, const float* __restrict__ b1,
                            const float* __restrict__ W2, const float* __restrict__ b2,
                            const float* __restrict__ W3, const float* __restrict__ b3,
                            float* __restrict__ out)
{
    __shared__ float v[256], u[256], w2s[64], lg[11];
    const int b = blockIdx.x, tid = threadIdx.x;

    v[tid] = last[b * 256 + tid];
    __syncthreads();

    float a = b1[tid];
    #pragma unroll 8
    for (int k = 0; k < 256; k++) a = fmaf(W1[tid * 256 + k], v[k], a);
    u[tid] = a;
    __syncthreads();

    if (tid < 64) {
        float s = b2[tid];
        #pragma unroll 8
        for (int k = 0; k < 256; k++) s = fmaf(W2[tid * 256 + k], u[k], s);
        w2s[tid] = s;
    }
    __syncthreads();

    if (tid < 11) {
        float s = b3[tid];
        #pragma unroll
        for (int k = 0; k < 64; k++) s = fmaf(W3[tid * 64 + k], w2s[k], s);
        lg[tid] = s;
    }
    __syncthreads();

    if (tid == 0) {
        float mx = lg[0];
        for (int i = 1; i < 11; i++) mx = fmaxf(mx, lg[i]);
        float e[11], sum = 0.0f;
        for (int i = 0; i < 11; i++) { e[i] = expf(lg[i] - mx); sum += e[i]; }
        const float inv = 1.0f / sum;
        for (int i = 0; i < 11; i++) out[b * 11 + i] = e[i] * inv;
    }
}

// ============================================================================
extern "C" void kernel_launch(void* const* d_in, const int* in_sizes, int n_in,
                              void* d_out, int out_size)
{
    const float* x    = (const float*)d_in[0];
    const float* Wihf = (const float*)d_in[1];
    const float* Whhf = (const float*)d_in[2];
    const float* bihf = (const float*)d_in[3];
    const float* bhhf = (const float*)d_in[4];
    const float* Wihb = (const float*)d_in[5];
    const float* bihb = (const float*)d_in[7];
    const float* bhhb = (const float*)d_in[8];
    const float* W1 = (const float*)d_in[9];   const float* b1 = (const float*)d_in[10];
    const float* W2 = (const float*)d_in[11];  const float* b2 = (const float*)d_in[12];
    const float* W3 = (const float*)d_in[13];  const float* b3 = (const float*)d_in[14];
    float* out = (float*)d_out;

    void* p;
    cudaGetSymbolAddress(&p, g_xp);   float*  xp   = (float*)p;
    cudaGetSymbolAddress(&p, g_last); float*  last = (float*)p;
    cudaGetSymbolAddress(&p, g_gb);   float*  gb   = (float*)p;
    cudaGetSymbolAddress(&p, g_Ah);   __half* Ah   = (__half*)p;
    cudaGetSymbolAddress(&p, g_Wh);   __half* Wh   = (__half*)p;

    const int gemm_smem = 3 * GSTAGE;   // 96 KB
    cudaFuncSetAttribute(gemm_h,    cudaFuncAttributeMaxDynamicSharedMemorySize, gemm_smem);
    cudaFuncSetAttribute(lstm_fwd5, cudaFuncAttributeMaxDynamicSharedMemorySize, LSTM_SMEM);

    // launch order puts gemm_h at index 3 = the ncu-profiled slot (bwd_fused
    // occupied index 3 in R8/R9 and was the profiled kernel both times)
    cvt_fp16<<<(M_FWD * D_) / 1024, 256>>>(x,    Ah, M_FWD * D_);          // 0
    cvt_fp16<<<(G_ * D_) / 1024,    256>>>(Wihf, Wh, G_ * D_);             // 1
    bwd_gemm<<<dim3(4, B_), 1024>>>(x, Wihb, bihb, bhhb, gb);              // 2
    gemm_h<<<dim3(G_ / 128, M_FWD / 128), 256, gemm_smem>>>(Ah, Wh, bihf, bhhf, xp); // 3
    lstm_fwd5<<<B_, 512, LSTM_SMEM>>>(xp, Whhf, last);                     // 4
    bwd_point<<<B_, 128>>>(gb, last);                                      // 5
    head_kernel<<<B_, 256>>>(last, W1, b1, W2, b2, W3, b3, out);           // 6
}

// round 11
// speedup vs baseline: 3.2428x; 1.0032x over previous
#include <cuda_runtime.h>
#include <cuda_fp16.h>
#include <cstdint>

#define B_  32
#define T_  512
#define D_  2048
#define H_  128
#define G_  512
#define M_FWD (B_ * T_)

typedef unsigned long long ull;

__device__ float  g_xp[M_FWD * G_];       // forward gate preacts [B*T, 4H]
__device__ float  g_last[B_ * 2 * H_];    // [h_fwd | h_bwd]
__device__ float  g_gb[B_ * 384];         // backward gate preacts (i|g|o rows)
__device__ __half g_Ah[M_FWD * D_];       // fp16 copy of inputs
__device__ __half g_Wh[G_ * D_];          // fp16 copy of W_ih_f

extern __shared__ unsigned char dynsmem[];

// ---------------- helpers ---------------------------------------------------
__device__ __forceinline__ uint32_t smem_u32(const void* p) {
    uint32_t a;
    asm("{ .reg .u64 t; cvta.to.shared.u64 t, %1; cvt.u32.u64 %0, t; }"
        : "=r"(a) : "l"(p));
    return a;
}
__device__ __forceinline__ void fma2(ull& d, ull a, ull b) {
    asm("fma.rn.f32x2 %0, %1, %2, %0;" : "+l"(d) : "l"(a), "l"(b));
}
__device__ __forceinline__ float2 unpk(ull v) {
    float2 r; asm("mov.b64 {%0,%1}, %2;" : "=f"(r.x), "=f"(r.y) : "l"(v)); return r;
}
__device__ __forceinline__ ull pk2(float2 v) {
    ull r; asm("mov.b64 %0, {%1,%2};" : "=l"(r) : "f"(v.x), "f"(v.y)); return r;
}
// precise activations (single-use sites: bwd step, 1 application — cheap)
__device__ __forceinline__ float fsig(float x)  { return 1.0f / (1.0f + expf(-x)); }
__device__ __forceinline__ float ftanh(float x) { return tanhf(x); }
// fast MUFU-EX2 activations for the 512-step recurrence (~2 ulp per use;
// contractive recurrence => <=1e-4 end-to-end, vs 1e-3 threshold)
__device__ __forceinline__ float esig(float x) {
    return __fdividef(1.0f, 1.0f + __expf(-x));
}
__device__ __forceinline__ float etanh(float x) {
    const float cx = fminf(fmaxf(x, -15.0f), 15.0f);   // avoid inf/inf
    const float e  = __expf(-2.0f * cx);
    return __fdividef(1.0f - e, 1.0f + e);
}

#define SWZ128(o) ((o) ^ (((o) >> 3) & 0x70))

#define LDSM_X4(r0, r1, r2, r3, a) \
    asm volatile("ldmatrix.sync.aligned.m8n8.x4.shared.b16 {%0,%1,%2,%3}, [%4];" \
                 : "=r"(r0), "=r"(r1), "=r"(r2), "=r"(r3) : "r"(a))

#define MMA16816(d, a, b) \
    asm volatile("mma.sync.aligned.m16n8k16.row.col.f32.f16.f16.f32 " \
        "{%0,%1,%2,%3}, {%4,%5,%6,%7}, {%8,%9}, {%0,%1,%2,%3};" \
        : "+f"((d)[0]), "+f"((d)[1]), "+f"((d)[2]), "+f"((d)[3]) \
        : "r"((a)[0]), "r"((a)[1]), "r"((a)[2]), "r"((a)[3]), \
          "r"((b)[0]), "r"((b)[1]))

#define CP_ASYNC16(sa, gp) \
    asm volatile("cp.async.ca.shared.global [%0], [%1], 16;" \
                 :: "r"(sa), "l"(gp) : "memory")
#define CP_COMMIT()  asm volatile("cp.async.commit_group;" ::: "memory")
#define CP_WAIT(n)   asm volatile("cp.async.wait_group %0;" :: "n"(n) : "memory")

// ============================================================================
// fp32 -> fp16 convert
// ============================================================================
__global__ __launch_bounds__(256)
void cvt_fp16(const float* __restrict__ src, __half* __restrict__ dst, int n)
{
    const int i = (blockIdx.x * 256 + threadIdx.x) * 4;
    if (i < n) {
        const float4 v = *(const float4*)(src + i);
        *(__half2*)(dst + i)     = __floats2half2_rn(v.x, v.y);
        *(__half2*)(dst + i + 2) = __floats2half2_rn(v.z, v.w);
    }
}

// ============================================================================
// fp16 GEMM (unchanged from R10: cp.async 3-stage + ldmatrix/mma, 107.7 us)
// ============================================================================
#define GSTAGE 32768
#define GNIT   (D_ / 64)    // 32

__global__ __launch_bounds__(256)
void gemm_h(const __half* __restrict__ Ah, const __half* __restrict__ Wh,
            const float* __restrict__ bias0, const float* __restrict__ bias1,
            float* __restrict__ C)
{
    __shared__ float sb[128];
    char* sm = (char*)dynsmem;
    const uint32_t smu = smem_u32(sm);

    const int tid  = threadIdx.x;
    const int wid  = tid >> 5, lane = tid & 31;
    const int wm   = wid & 3,  wn   = wid >> 2;
    const int g    = lane >> 2, tg  = lane & 3;
    const int n0   = blockIdx.x * 128;
    const int m0   = blockIdx.y * 128;

    if (tid < 128) sb[tid] = bias0[n0 + tid] + bias1[n0 + tid];

    const int arow  = wm * 32 + (lane & 15);
    const int acsel = (lane & 16) ? 16 : 0;
    const int brow  = wn * 64 + (lane & 7) + ((lane & 16) ? 8 : 0);
    const int bcsel = (lane & 8) ? 16 : 0;

    const __half* Ab = Ah + (long)m0 * D_;
    const __half* Wb = Wh + (long)n0 * D_;

    const int sr0 = tid >> 3;
    const int sc8 = tid & 7;

    #define ISSUE_STAGE(s, kt) do {                                           \
        const uint32_t _st = smu + (s) * GSTAGE;                              \
        const long _k = (long)(kt) * 64;                                      \
        _Pragma("unroll")                                                     \
        for (int _i = 0; _i < 4; _i++) {                                      \
            const int _r = sr0 + _i * 32;                                     \
            const uint32_t _off = SWZ128(_r * 128 + sc8 * 16);                \
            CP_ASYNC16(_st + _off,         Ab + (long)_r * D_ + _k + sc8 * 8);\
            CP_ASYNC16(_st + 16384 + _off, Wb + (long)_r * D_ + _k + sc8 * 8);\
        }                                                                     \
    } while (0)

    ISSUE_STAGE(0, 0); CP_COMMIT();
    ISSUE_STAGE(1, 1); CP_COMMIT();

    float acc[2][8][4];
    #pragma unroll
    for (int i = 0; i < 2; i++)
        #pragma unroll
        for (int j = 0; j < 8; j++)
            #pragma unroll
            for (int r = 0; r < 4; r++) acc[i][j][r] = 0.0f;

    for (int it = 0; it < GNIT; it++) {
        if (it + 1 < GNIT) CP_WAIT(1); else CP_WAIT(0);
        __syncthreads();
        if (it + 2 < GNIT) { ISSUE_STAGE((it + 2) % 3, it + 2); CP_COMMIT(); }

        const uint32_t a_st = smu + (it % 3) * GSTAGE;
        const uint32_t b_st = a_st + 16384;
        #pragma unroll
        for (int kk = 0; kk < 4; kk++) {
            uint32_t af[2][4], bf[8][2];
            #pragma unroll
            for (int mf = 0; mf < 2; mf++) {
                const uint32_t off =
                    SWZ128((arow + mf * 16) * 128 + kk * 32 + acsel);
                LDSM_X4(af[mf][0], af[mf][1], af[mf][2], af[mf][3], a_st + off);
            }
            #pragma unroll
            for (int np = 0; np < 4; np++) {
                const uint32_t off =
                    SWZ128((brow + np * 16) * 128 + kk * 32 + bcsel);
                uint32_t r0, r1, r2, r3;
                LDSM_X4(r0, r1, r2, r3, b_st + off);
                bf[2 * np][0] = r0;     bf[2 * np][1] = r1;
                bf[2 * np + 1][0] = r2; bf[2 * np + 1][1] = r3;
            }
            #pragma unroll
            for (int mf = 0; mf < 2; mf++)
                #pragma unroll
                for (int nf = 0; nf < 8; nf++)
                    MMA16816(acc[mf][nf], af[mf], bf[nf]);
        }
    }

    #pragma unroll
    for (int mf = 0; mf < 2; mf++) {
        #pragma unroll
        for (int nf = 0; nf < 8; nf++) {
            const int cl  = wn * 64 + nf * 8 + 2 * tg;
            const float b0v = sb[cl], b1v = sb[cl + 1];
            const int r0 = m0 + wm * 32 + mf * 16 + g;
            float2 v0; v0.x = acc[mf][nf][0] + b0v; v0.y = acc[mf][nf][1] + b1v;
            *(float2*)(C + (long)r0 * G_ + n0 + cl) = v0;
            float2 v1; v1.x = acc[mf][nf][2] + b0v; v1.y = acc[mf][nf][3] + b1v;
            *(float2*)(C + (long)(r0 + 8) * G_ + n0 + cl) = v1;
        }
    }
}

// ============================================================================
// Forward LSTM recurrence v6: R9 structure + MUFU-EX2 activations.
// One CTA/batch, 512 threads, one thread per gate row; W head (k<80) in 40
// f32x2 regs, tail (k>=80) fp16 smem transposed; per-row activation spread
// over all 512 threads pre-barrier; tail c-update with __expf tanh.
// ============================================================================
#define WTAIL_CH 12
#define LSTM_SMEM ((128 + 512) * 4 + WTAIL_CH * 512 * 8)   // 51,712 B

__global__ __launch_bounds__(512)
void lstm_fwd6(const float* __restrict__ xp, const float* __restrict__ Whh,
               float* __restrict__ last)
{
    float* h_s    = (float*)dynsmem;               // [128]
    float* gate_s = h_s + 128;                     // [512] (activated gates)
    ull*   Wt     = (ull*)(gate_s + 512);          // [12][512], 4 halves each

    const int tid = threadIdx.x;        // == gate row
    const int b   = blockIdx.x;
    const bool is_g = (tid >= 256) && (tid < 384);

    #pragma unroll
    for (int j = 0; j < WTAIL_CH; j++) {
        const float4 wv = *(const float4*)(Whh + tid * 128 + 80 + 4 * j);
        uint2 u;
        *(__half2*)&u.x = __floats2half2_rn(wv.x, wv.y);
        *(__half2*)&u.y = __floats2half2_rn(wv.z, wv.w);
        Wt[j * 512 + tid] = *(ull*)&u;
    }
    ull w[40];
    {
        const ull* wr = (const ull*)(Whh + tid * 128);
        #pragma unroll
        for (int i = 0; i < 40; i++) w[i] = wr[i];
    }
    if (tid < 128) h_s[tid] = 0.0f;
    float c = 0.0f;
    __syncthreads();

    const float* xprow = xp + (long)b * T_ * G_ + tid;
    float xv = xprow[0];

    for (int t = 0; t < T_; t++) {
        const ulonglong2* hp = (const ulonglong2*)h_s;
        ull a0 = 0, a1 = 0, a2 = 0, a3 = 0;
        #pragma unroll
        for (int i = 0; i < 20; i++) {                   // k 0..79 (registers)
            const ulonglong2 hv = hp[i];
            fma2(a0, w[2 * i],     hv.x);
            fma2(a1, w[2 * i + 1], hv.y);
        }
        #pragma unroll
        for (int j = 0; j < WTAIL_CH; j++) {             // k 80..127 (fp16 smem)
            const ull wv = Wt[j * 512 + tid];
            const uint2 u = *(const uint2*)&wv;
            const ulonglong2 hv = hp[20 + j];
            fma2(a2, pk2(__half22float2(*(const __half2*)&u.x)), hv.x);
            fma2(a3, pk2(__half22float2(*(const __half2*)&u.y)), hv.y);
        }
        const float2 f0 = unpk(a0), f1 = unpk(a1);
        const float2 f2v = unpk(a2), f3 = unpk(a3);
        const float pre = xv + ((f0.x + f0.y) + (f1.x + f1.y))
                             + ((f2v.x + f2v.y) + (f3.x + f3.y));
        gate_s[tid] = is_g ? etanh(pre) : esig(pre);     // fast activation
        if (t + 1 < T_) xv = xprow[(long)(t + 1) * G_];
        __syncthreads();
        if (tid < 128) {
            const float ai = gate_s[tid],       af = gate_s[128 + tid];
            const float ag = gate_s[256 + tid], ao = gate_s[384 + tid];
            c = af * c + ai * ag;
            const float h = ao * etanh(c);               // fast tail tanh
            h_s[tid] = h;
            if (t == T_ - 1) last[b * (2 * H_) + tid] = h;
        }
        __syncthreads();
    }
}

// ============================================================================
// Backward direction (unchanged from R10): one step from zero state,
// 128 CTAs, warp-per-3-rows; then pointwise.
// ============================================================================
__global__ __launch_bounds__(1024)
void bwd_gemm(const float* __restrict__ x, const float* __restrict__ Wihb,
              const float* __restrict__ bihb, const float* __restrict__ bhhb,
              float* __restrict__ gb)
{
    __shared__ float xs[2048];
    const int b = blockIdx.y, slice = blockIdx.x;
    const int tid = threadIdx.x, warp = tid >> 5, lane = tid & 31;

    const float* xr = x + ((long)b * T_ + (T_ - 1)) * D_;
    for (int i = tid; i < 2048; i += 1024) xs[i] = xr[i];
    __syncthreads();

    #pragma unroll
    for (int jj = 0; jj < 3; jj++) {
        const int j = slice * 96 + warp * 3 + jj;     // 0..383
        const int r = (j < 128) ? j : (j + 128);      // skip f rows
        const float4* wr = (const float4*)(Wihb + (long)r * D_);
        float s = 0.0f;
        #pragma unroll
        for (int it = 0; it < 16; it++) {
            const float4 wv = wr[it * 32 + lane];
            const float4 hx = *(const float4*)(xs + 4 * (it * 32 + lane));
            s += wv.x * hx.x + wv.y * hx.y + wv.z * hx.z + wv.w * hx.w;
        }
        #pragma unroll
        for (int d = 16; d > 0; d >>= 1)
            s += __shfl_xor_sync(0xFFFFFFFFu, s, d);
        if (lane == 0) gb[b * 384 + j] = s + bihb[r] + bhhb[r];
    }
}

__global__ void bwd_point(const float* __restrict__ gb, float* __restrict__ last)
{
    const int b = blockIdx.x, j = threadIdx.x;   // 32 x 128
    const float* r = gb + b * 384;
    const float ci = fsig(r[j]) * ftanh(r[128 + j]);
    last[b * (2 * H_) + H_ + j] = fsig(r[256 + j]) * ftanh(ci);
}

// ============================================================================
// MLP head + softmax.
// ============================================================================
__global__ void head_kernel(const float* __restrict__ last,
                            const float* __restrict__ W1, const float* __restrict__ b1,
                            const float* __restrict__ W2, const float* __restrict__ b2,
                            const float* __restrict__ W3, const float* __restrict__ b3,
                            float* __restrict__ out)
{
    __shared__ float v[256], u[256], w2s[64], lg[11];
    const int b = blockIdx.x, tid = threadIdx.x;

    v[tid] = last[b * 256 + tid];
    __syncthreads();

    float a = b1[tid];
    #pragma unroll 8
    for (int k = 0; k < 256; k++) a = fmaf(W1[tid * 256 + k], v[k], a);
    u[tid] = a;
    __syncthreads();

    if (tid < 64) {
        float s = b2[tid];
        #pragma unroll 8
        for (int k = 0; k < 256; k++) s = fmaf(W2[tid * 256 + k], u[k], s);
        w2s[tid] = s;
    }
    __syncthreads();

    if (tid < 11) {
        float s = b3[tid];
        #pragma unroll
        for (int k = 0; k < 64; k++) s = fmaf(W3[tid * 64 + k], w2s[k], s);
        lg[tid] = s;
    }
    __syncthreads();

    if (tid == 0) {
        float mx = lg[0];
        for (int i = 1; i < 11; i++) mx = fmaxf(mx, lg[i]);
        float e[11], sum = 0.0f;
        for (int i = 0; i < 11; i++) { e[i] = expf(lg[i] - mx); sum += e[i]; }
        const float inv = 1.0f / sum;
        for (int i = 0; i < 11; i++) out[b * 11 + i] = e[i] * inv;
    }
}

// ============================================================================
extern "C" void kernel_launch(void* const* d_in, const int* in_sizes, int n_in,
                              void* d_out, int out_size)
{
    const float* x    = (const float*)d_in[0];
    const float* Wihf = (const float*)d_in[1];
    const float* Whhf = (const float*)d_in[2];
    const float* bihf = (const float*)d_in[3];
    const float* bhhf = (const float*)d_in[4];
    const float* Wihb = (const float*)d_in[5];
    const float* bihb = (const float*)d_in[7];
    const float* bhhb = (const float*)d_in[8];
    const float* W1 = (const float*)d_in[9];   const float* b1 = (const float*)d_in[10];
    const float* W2 = (const float*)d_in[11];  const float* b2 = (const float*)d_in[12];
    const float* W3 = (const float*)d_in[13];  const float* b3 = (const float*)d_in[14];
    float* out = (float*)d_out;

    void* p;
    cudaGetSymbolAddress(&p, g_xp);   float*  xp   = (float*)p;
    cudaGetSymbolAddress(&p, g_last); float*  last = (float*)p;
    cudaGetSymbolAddress(&p, g_gb);   float*  gb   = (float*)p;
    cudaGetSymbolAddress(&p, g_Ah);   __half* Ah   = (__half*)p;
    cudaGetSymbolAddress(&p, g_Wh);   __half* Wh   = (__half*)p;

    const int gemm_smem = 3 * GSTAGE;   // 96 KB
    cudaFuncSetAttribute(gemm_h,    cudaFuncAttributeMaxDynamicSharedMemorySize, gemm_smem);
    cudaFuncSetAttribute(lstm_fwd6, cudaFuncAttributeMaxDynamicSharedMemorySize, LSTM_SMEM);

    // launch order: lstm at index 3 == the ncu-profiled slot (confirmed
    // across R1/R8/R9/R10); gemm (its producer) runs before it.
    cvt_fp16<<<(M_FWD * D_) / 1024, 256>>>(x,    Ah, M_FWD * D_);          // 0
    cvt_fp16<<<(G_ * D_) / 1024,    256>>>(Wihf, Wh, G_ * D_);             // 1
    gemm_h<<<dim3(G_ / 128, M_FWD / 128), 256, gemm_smem>>>(Ah, Wh, bihf, bhhf, xp); // 2
    lstm_fwd6<<<B_, 512, LSTM_SMEM>>>(xp, Whhf, last);                     // 3
    bwd_gemm<<<dim3(4, B_), 1024>>>(x, Wihb, bihb, bhhb, gb);              // 4
    bwd_point<<<B_, 128>>>(gb, last);                                      // 5
    head_kernel<<<B_, 256>>>(last, W1, b1, W2, b2, W3, b3, out);           // 6
}

// round 12
// speedup vs baseline: 4.4166x; 1.3620x over previous
#include <cuda_runtime.h>
#include <cuda_fp16.h>
#include <cstdint>

#define B_  32
#define T_  512
#define D_  2048
#define H_  128
#define G_  512
#define M_FWD (B_ * T_)

typedef unsigned long long ull;

__device__ float  g_xp[M_FWD * G_];       // forward gate preacts [B*T, 4H]
__device__ float  g_last[B_ * 2 * H_];    // [h_fwd | h_bwd]
__device__ float  g_gb[B_ * 384];         // backward gate preacts (i|g|o rows)
__device__ __half g_Ah[M_FWD * D_];       // fp16 copy of inputs
__device__ __half g_Wh[G_ * D_];          // fp16 copy of W_ih_f

extern __shared__ unsigned char dynsmem[];

// ---------------- helpers ---------------------------------------------------
__device__ __forceinline__ uint32_t smem_u32(const void* p) {
    uint32_t a;
    asm("{ .reg .u64 t; cvta.to.shared.u64 t, %1; cvt.u32.u64 %0, t; }"
        : "=r"(a) : "l"(p));
    return a;
}
// precise activations for single-use sites
__device__ __forceinline__ float fsig(float x)  { return 1.0f / (1.0f + expf(-x)); }
__device__ __forceinline__ float ftanh(float x) { return tanhf(x); }
// MUFU-EX2 activations for the recurrence (verified neutral on rel_err in R11)
__device__ __forceinline__ float esig(float x) {
    return __fdividef(1.0f, 1.0f + __expf(-x));
}
__device__ __forceinline__ float etanh(float x) {
    const float cx = fminf(fmaxf(x, -15.0f), 15.0f);
    const float e  = __expf(-2.0f * cx);
    return __fdividef(1.0f - e, 1.0f + e);
}
__device__ __forceinline__ uint32_t h2pack(float2 v) {
    __half2 h = __floats2half2_rn(v.x, v.y);
    return *(uint32_t*)&h;
}

#define SWZ128(o) ((o) ^ (((o) >> 3) & 0x70))

#define LDSM_X4(r0, r1, r2, r3, a) \
    asm volatile("ldmatrix.sync.aligned.m8n8.x4.shared.b16 {%0,%1,%2,%3}, [%4];" \
                 : "=r"(r0), "=r"(r1), "=r"(r2), "=r"(r3) : "r"(a))

#define MMA16816(d, a, b) \
    asm volatile("mma.sync.aligned.m16n8k16.row.col.f32.f16.f16.f32 " \
        "{%0,%1,%2,%3}, {%4,%5,%6,%7}, {%8,%9}, {%0,%1,%2,%3};" \
        : "+f"((d)[0]), "+f"((d)[1]), "+f"((d)[2]), "+f"((d)[3]) \
        : "r"((a)[0]), "r"((a)[1]), "r"((a)[2]), "r"((a)[3]), \
          "r"((b)[0]), "r"((b)[1]))

#define CP_ASYNC16(sa, gp) \
    asm volatile("cp.async.ca.shared.global [%0], [%1], 16;" \
                 :: "r"(sa), "l"(gp) : "memory")
#define CP_COMMIT()  asm volatile("cp.async.commit_group;" ::: "memory")
#define CP_WAIT(n)   asm volatile("cp.async.wait_group %0;" :: "n"(n) : "memory")

// ============================================================================
// fp32 -> fp16 convert
// ============================================================================
__global__ __launch_bounds__(256)
void cvt_fp16(const float* __restrict__ src, __half* __restrict__ dst, int n)
{
    const int i = (blockIdx.x * 256 + threadIdx.x) * 4;
    if (i < n) {
        const float4 v = *(const float4*)(src + i);
        *(__half2*)(dst + i)     = __floats2half2_rn(v.x, v.y);
        *(__half2*)(dst + i + 2) = __floats2half2_rn(v.z, v.w);
    }
}

// ============================================================================
// fp16 GEMM (unchanged from R10/R11: cp.async 3-stage + ldmatrix/mma, 108 us)
// ============================================================================
#define GSTAGE 32768
#define GNIT   (D_ / 64)    // 32

__global__ __launch_bounds__(256)
void gemm_h(const __half* __restrict__ Ah, const __half* __restrict__ Wh,
            const float* __restrict__ bias0, const float* __restrict__ bias1,
            float* __restrict__ C)
{
    __shared__ float sb[128];
    char* sm = (char*)dynsmem;
    const uint32_t smu = smem_u32(sm);

    const int tid  = threadIdx.x;
    const int wid  = tid >> 5, lane = tid & 31;
    const int wm   = wid & 3,  wn   = wid >> 2;
    const int g    = lane >> 2, tg  = lane & 3;
    const int n0   = blockIdx.x * 128;
    const int m0   = blockIdx.y * 128;

    if (tid < 128) sb[tid] = bias0[n0 + tid] + bias1[n0 + tid];

    const int arow  = wm * 32 + (lane & 15);
    const int acsel = (lane & 16) ? 16 : 0;
    const int brow  = wn * 64 + (lane & 7) + ((lane & 16) ? 8 : 0);
    const int bcsel = (lane & 8) ? 16 : 0;

    const __half* Ab = Ah + (long)m0 * D_;
    const __half* Wb = Wh + (long)n0 * D_;

    const int sr0 = tid >> 3;
    const int sc8 = tid & 7;

    #define ISSUE_STAGE(s, kt) do {                                           \
        const uint32_t _st = smu + (s) * GSTAGE;                              \
        const long _k = (long)(kt) * 64;                                      \
        _Pragma("unroll")                                                     \
        for (int _i = 0; _i < 4; _i++) {                                      \
            const int _r = sr0 + _i * 32;                                     \
            const uint32_t _off = SWZ128(_r * 128 + sc8 * 16);                \
            CP_ASYNC16(_st + _off,         Ab + (long)_r * D_ + _k + sc8 * 8);\
            CP_ASYNC16(_st + 16384 + _off, Wb + (long)_r * D_ + _k + sc8 * 8);\
        }                                                                     \
    } while (0)

    ISSUE_STAGE(0, 0); CP_COMMIT();
    ISSUE_STAGE(1, 1); CP_COMMIT();

    float acc[2][8][4];
    #pragma unroll
    for (int i = 0; i < 2; i++)
        #pragma unroll
        for (int j = 0; j < 8; j++)
            #pragma unroll
            for (int r = 0; r < 4; r++) acc[i][j][r] = 0.0f;

    for (int it = 0; it < GNIT; it++) {
        if (it + 1 < GNIT) CP_WAIT(1); else CP_WAIT(0);
        __syncthreads();
        if (it + 2 < GNIT) { ISSUE_STAGE((it + 2) % 3, it + 2); CP_COMMIT(); }

        const uint32_t a_st = smu + (it % 3) * GSTAGE;
        const uint32_t b_st = a_st + 16384;
        #pragma unroll
        for (int kk = 0; kk < 4; kk++) {
            uint32_t af[2][4], bf[8][2];
            #pragma unroll
            for (int mf = 0; mf < 2; mf++) {
                const uint32_t off =
                    SWZ128((arow + mf * 16) * 128 + kk * 32 + acsel);
                LDSM_X4(af[mf][0], af[mf][1], af[mf][2], af[mf][3], a_st + off);
            }
            #pragma unroll
            for (int np = 0; np < 4; np++) {
                const uint32_t off =
                    SWZ128((brow + np * 16) * 128 + kk * 32 + bcsel);
                uint32_t r0, r1, r2, r3;
                LDSM_X4(r0, r1, r2, r3, b_st + off);
                bf[2 * np][0] = r0;     bf[2 * np][1] = r1;
                bf[2 * np + 1][0] = r2; bf[2 * np + 1][1] = r3;
            }
            #pragma unroll
            for (int mf = 0; mf < 2; mf++)
                #pragma unroll
                for (int nf = 0; nf < 8; nf++)
                    MMA16816(acc[mf][nf], af[mf], bf[nf]);
        }
    }

    #pragma unroll
    for (int mf = 0; mf < 2; mf++) {
        #pragma unroll
        for (int nf = 0; nf < 8; nf++) {
            const int cl  = wn * 64 + nf * 8 + 2 * tg;
            const float b0v = sb[cl], b1v = sb[cl + 1];
            const int r0 = m0 + wm * 32 + mf * 16 + g;
            float2 v0; v0.x = acc[mf][nf][0] + b0v; v0.y = acc[mf][nf][1] + b1v;
            *(float2*)(C + (long)r0 * G_ + n0 + cl) = v0;
            float2 v1; v1.x = acc[mf][nf][2] + b0v; v1.y = acc[mf][nf][3] + b1v;
            *(float2*)(C + (long)(r0 + 8) * G_ + n0 + cl) = v1;
        }
    }
}

// ============================================================================
// Forward LSTM recurrence v7 — HMMA. One CTA/batch, 512 threads = 16 warps.
// gates[512] = Whh[512x128] @ h[128] as m16n8k16 mma with N=1: all 8 B
// columns are fed the SAME h values, so all acc columns are identical.
// W_hh preloaded ONCE into 64 a-fragment registers (fp16). h lives in smem
// as fp16 (written by the pointwise threads). acc initialized to xp[t]
// (which already contains both biases). Fragment layouts match the verified
// gemm_h conventions:
//   a0=(row g, k 2tg..), a1=(row g+8), a2=(row g, k+8), a3=(row g+8, k+8)
//   b0=(k 2tg..),        b1=(k 2tg+8..)            [n = g, irrelevant here]
//   c0,c1=(row g),       c2,c3=(row g+8)
// ============================================================================
__global__ __launch_bounds__(512)
void lstm_hmma(const float* __restrict__ xp, const float* __restrict__ Whh,
               float* __restrict__ last)
{
    __shared__ __align__(16) __half h16[128];
    __shared__ float gate_s[512];

    const int tid = threadIdx.x, b = blockIdx.x;
    const int wid = tid >> 5, lane = tid & 31;
    const int g   = lane >> 2, tg = lane & 3;
    const int r0  = wid * 32 + g;       // this lane's tile-0 base row

    // ---- preload W_hh into a-fragments (one time; fp32->fp16 on load) ----
    uint32_t af[2][8][4];
    #pragma unroll
    for (int m = 0; m < 2; m++) {
        const float* wr0 = Whh + (r0 + 16 * m) * 128;
        const float* wr1 = wr0 + 8 * 128;
        #pragma unroll
        for (int ks = 0; ks < 8; ks++) {
            af[m][ks][0] = h2pack(*(const float2*)(wr0 + 16 * ks + 2 * tg));
            af[m][ks][1] = h2pack(*(const float2*)(wr1 + 16 * ks + 2 * tg));
            af[m][ks][2] = h2pack(*(const float2*)(wr0 + 16 * ks + 8 + 2 * tg));
            af[m][ks][3] = h2pack(*(const float2*)(wr1 + 16 * ks + 8 + 2 * tg));
        }
    }
    if (tid < 128) h16[tid] = __float2half_rn(0.0f);
    float c = 0.0f;
    __syncthreads();

    const float* xpb = xp + (long)b * T_ * G_;
    float xv[2][2];
    #pragma unroll
    for (int m = 0; m < 2; m++) {
        xv[m][0] = xpb[r0 + 16 * m];
        xv[m][1] = xpb[r0 + 16 * m + 8];
    }

    for (int t = 0; t < T_; t++) {
        float acc0[4] = { xv[0][0], xv[0][0], xv[0][1], xv[0][1] };
        float acc1[4] = { xv[1][0], xv[1][0], xv[1][1], xv[1][1] };
        #pragma unroll
        for (int ks = 0; ks < 8; ks++) {
            uint32_t bf[2];
            bf[0] = *(const uint32_t*)(h16 + 16 * ks + 2 * tg);      // k 0..7
            bf[1] = *(const uint32_t*)(h16 + 16 * ks + 8 + 2 * tg);  // k 8..15
            MMA16816(acc0, af[0][ks], bf);
            MMA16816(acc1, af[1][ks], bf);
        }
        if (t + 1 < T_) {                        // prefetch next xp (L1/L2)
            const float* nx = xpb + (long)(t + 1) * G_;
            #pragma unroll
            for (int m = 0; m < 2; m++) {
                xv[m][0] = nx[r0 + 16 * m];
                xv[m][1] = nx[r0 + 16 * m + 8];
            }
        }
        if (tg == 0) {                            // all acc cols identical
            gate_s[r0]      = acc0[0];
            gate_s[r0 + 8]  = acc0[2];
            gate_s[r0 + 16] = acc1[0];
            gate_s[r0 + 24] = acc1[2];
        }
        __syncthreads();
        if (tid < 128) {
            const float gi = gate_s[tid],       gf = gate_s[128 + tid];
            const float gg = gate_s[256 + tid], go = gate_s[384 + tid];
            c = esig(gf) * c + esig(gi) * etanh(gg);
            const float h = esig(go) * etanh(c);
            h16[tid] = __float2half_rn(h);
            if (t == T_ - 1) last[b * (2 * H_) + tid] = h;
        }
        __syncthreads();
    }
}

// ============================================================================
// Backward direction (unchanged): one step from zero state, 128 CTAs.
// ============================================================================
__global__ __launch_bounds__(1024)
void bwd_gemm(const float* __restrict__ x, const float* __restrict__ Wihb,
              const float* __restrict__ bihb, const float* __restrict__ bhhb,
              float* __restrict__ gb)
{
    __shared__ float xs[2048];
    const int b = blockIdx.y, slice = blockIdx.x;
    const int tid = threadIdx.x, warp = tid >> 5, lane = tid & 31;

    const float* xr = x + ((long)b * T_ + (T_ - 1)) * D_;
    for (int i = tid; i < 2048; i += 1024) xs[i] = xr[i];
    __syncthreads();

    #pragma unroll
    for (int jj = 0; jj < 3; jj++) {
        const int j = slice * 96 + warp * 3 + jj;     // 0..383
        const int r = (j < 128) ? j : (j + 128);      // skip f rows
        const float4* wr = (const float4*)(Wihb + (long)r * D_);
        float s = 0.0f;
        #pragma unroll
        for (int it = 0; it < 16; it++) {
            const float4 wv = wr[it * 32 + lane];
            const float4 hx = *(const float4*)(xs + 4 * (it * 32 + lane));
            s += wv.x * hx.x + wv.y * hx.y + wv.z * hx.z + wv.w * hx.w;
        }
        #pragma unroll
        for (int d = 16; d > 0; d >>= 1)
            s += __shfl_xor_sync(0xFFFFFFFFu, s, d);
        if (lane == 0) gb[b * 384 + j] = s + bihb[r] + bhhb[r];
    }
}

__global__ void bwd_point(const float* __restrict__ gb, float* __restrict__ last)
{
    const int b = blockIdx.x, j = threadIdx.x;   // 32 x 128
    const float* r = gb + b * 384;
    const float ci = fsig(r[j]) * ftanh(r[128 + j]);
    last[b * (2 * H_) + H_ + j] = fsig(r[256 + j]) * ftanh(ci);
}

// ============================================================================
// MLP head + softmax.
// ============================================================================
__global__ void head_kernel(const float* __restrict__ last,
                            const float* __restrict__ W1, const float* __restrict__ b1,
                            const float* __restrict__ W2, const float* __restrict__ b2,
                            const float* __restrict__ W3, const float* __restrict__ b3,
                            float* __restrict__ out)
{
    __shared__ float v[256], u[256], w2s[64], lg[11];
    const int b = blockIdx.x, tid = threadIdx.x;

    v[tid] = last[b * 256 + tid];
    __syncthreads();

    float a = b1[tid];
    #pragma unroll 8
    for (int k = 0; k < 256; k++) a = fmaf(W1[tid * 256 + k], v[k], a);
    u[tid] = a;
    __syncthreads();

    if (tid < 64) {
        float s = b2[tid];
        #pragma unroll 8
        for (int k = 0; k < 256; k++) s = fmaf(W2[tid * 256 + k], u[k], s);
        w2s[tid] = s;
    }
    __syncthreads();

    if (tid < 11) {
        float s = b3[tid];
        #pragma unroll
        for (int k = 0; k < 64; k++) s = fmaf(W3[tid * 64 + k], w2s[k], s);
        lg[tid] = s;
    }
    __syncthreads();

    if (tid == 0) {
        float mx = lg[0];
        for (int i = 1; i < 11; i++) mx = fmaxf(mx, lg[i]);
        float e[11], sum = 0.0f;
        for (int i = 0; i < 11; i++) { e[i] = expf(lg[i] - mx); sum += e[i]; }
        const float inv = 1.0f / sum;
        for (int i = 0; i < 11; i++) out[b * 11 + i] = e[i] * inv;
    }
}

// ============================================================================
extern "C" void kernel_launch(void* const* d_in, const int* in_sizes, int n_in,
                              void* d_out, int out_size)
{
    const float* x    = (const float*)d_in[0];
    const float* Wihf = (const float*)d_in[1];
    const float* Whhf = (const float*)d_in[2];
    const float* bihf = (const float*)d_in[3];
    const float* bhhf = (const float*)d_in[4];
    const float* Wihb = (const float*)d_in[5];
    const float* bihb = (const float*)d_in[7];
    const float* bhhb = (const float*)d_in[8];
    const float* W1 = (const float*)d_in[9];   const float* b1 = (const float*)d_in[10];
    const float* W2 = (const float*)d_in[11];  const float* b2 = (const float*)d_in[12];
    const float* W3 = (const float*)d_in[13];  const float* b3 = (const float*)d_in[14];
    float* out = (float*)d_out;

    void* p;
    cudaGetSymbolAddress(&p, g_xp);   float*  xp   = (float*)p;
    cudaGetSymbolAddress(&p, g_last); float*  last = (float*)p;
    cudaGetSymbolAddress(&p, g_gb);   float*  gb   = (float*)p;
    cudaGetSymbolAddress(&p, g_Ah);   __half* Ah   = (__half*)p;
    cudaGetSymbolAddress(&p, g_Wh);   __half* Wh   = (__half*)p;

    const int gemm_smem = 3 * GSTAGE;   // 96 KB
    cudaFuncSetAttribute(gemm_h, cudaFuncAttributeMaxDynamicSharedMemorySize, gemm_smem);

    // lstm at index 3 == the ncu-profiled slot (confirmed R1/R8-R11)
    cvt_fp16<<<(M_FWD * D_) / 1024, 256>>>(x,    Ah, M_FWD * D_);          // 0
    cvt_fp16<<<(G_ * D_) / 1024,    256>>>(Wihf, Wh, G_ * D_);             // 1
    gemm_h<<<dim3(G_ / 128, M_FWD / 128), 256, gemm_smem>>>(Ah, Wh, bihf, bhhf, xp); // 2
    lstm_hmma<<<B_, 512>>>(xp, Whhf, last);                                // 3
    bwd_gemm<<<dim3(4, B_), 1024>>>(x, Wihb, bihb, bhhb, gb);              // 4
    bwd_point<<<B_, 128>>>(gb, last);                                      // 5
    head_kernel<<<B_, 256>>>(last, W1, b1, W2, b2, W3, b3, out);           // 6
}